// round 1
// baseline (speedup 1.0000x reference)
#include <cuda_runtime.h>
#include <math.h>

// Problem constants
#define NB 4
#define NS 8192
#define NHID 768
#define NH 12
#define ND 64
#define NK 16
#define NMB (NS/NK)          // 512
#define NTOK (NB*NS)         // 32768

// ---------------- scratch (device globals; no allocs allowed) ----------------
__device__ float g_xqk[NTOK*NHID];   // x@wq ; later reused as G = Zn*gelu(gate)
__device__ float g_xvr[NTOK*NHID];   // x@wv raw [B,S,HID]
__device__ float g_gate[NTOK*NHID];  // x@wg raw
__device__ float g_xq[NTOK*NHID];    // [B,H,S,D] conv+rope
__device__ float g_xk[NTOK*NHID];    // [B,H,S,D]
__device__ float g_xv[NTOK*NHID];    // [B,H,S,D]
__device__ float g_Z[NTOK*NHID];     // scan output [B,S,H*D]
__device__ float g_eta[NB*NH*NS];    // ttt_lr_eta = sigmoid(.)/D, [B,H,S]

__device__ __forceinline__ float warpAllSum(float v) {
#pragma unroll
    for (int o = 16; o; o >>= 1) v += __shfl_xor_sync(0xffffffffu, v, o);
    return v;
}

// ---------------- SGEMM: C[M,N] = A[M,K] * B[K,N], fp32, 128x128x8 tiles ------
__global__ __launch_bounds__(256) void sgemm128(
    const float* __restrict__ A, const float* __restrict__ B,
    float* __restrict__ C, int M, int N, int Kd)
{
    __shared__ float As[8][128];
    __shared__ float Bs[8][128];
    int tid = threadIdx.x;
    int cx = blockIdx.x * 128;
    int ry = blockIdx.y * 128;

    int arow = tid >> 1, ak = (tid & 1) * 4;       // A: 128 rows x 8 k
    int brow = tid >> 5, bc = (tid & 31) * 4;      // B: 8 rows x 128 cols
    const float* Ap = A + (size_t)(ry + arow) * Kd + ak;
    const float* Bp = B + (size_t)brow * N + cx + bc;

    int tx = tid & 15, ty = tid >> 4;
    float acc[8][8];
#pragma unroll
    for (int i = 0; i < 8; i++)
#pragma unroll
        for (int j = 0; j < 8; j++) acc[i][j] = 0.f;

    for (int k0 = 0; k0 < Kd; k0 += 8) {
        float4 a4 = *(const float4*)(Ap + k0);
        As[ak + 0][arow] = a4.x; As[ak + 1][arow] = a4.y;
        As[ak + 2][arow] = a4.z; As[ak + 3][arow] = a4.w;
        *(float4*)&Bs[brow][bc] = *(const float4*)(Bp + (size_t)k0 * N);
        __syncthreads();
#pragma unroll
        for (int kk = 0; kk < 8; kk++) {
            float ar[8], br[8];
            *(float4*)(ar)     = *(const float4*)&As[kk][ty * 8];
            *(float4*)(ar + 4) = *(const float4*)&As[kk][ty * 8 + 4];
            *(float4*)(br)     = *(const float4*)&Bs[kk][tx * 8];
            *(float4*)(br + 4) = *(const float4*)&Bs[kk][tx * 8 + 4];
#pragma unroll
            for (int i = 0; i < 8; i++)
#pragma unroll
                for (int j = 0; j < 8; j++) acc[i][j] += ar[i] * br[j];
        }
        __syncthreads();
    }
#pragma unroll
    for (int i = 0; i < 8; i++) {
        float* cp = C + (size_t)(ry + ty * 8 + i) * N + cx + tx * 8;
        *(float4*)(cp)     = make_float4(acc[i][0], acc[i][1], acc[i][2], acc[i][3]);
        *(float4*)(cp + 4) = make_float4(acc[i][4], acc[i][5], acc[i][6], acc[i][7]);
    }
}

// ---------------- ttt_lr_eta = sigmoid(x . lr_w[h] + lr_b[h]) / D -------------
__global__ __launch_bounds__(256) void lr_kernel(
    const float* __restrict__ x, const float* __restrict__ lrw,
    const float* __restrict__ lrb)
{
    int gw = (blockIdx.x * blockDim.x + threadIdx.x) >> 5;   // token id
    int lane = threadIdx.x & 31;
    const float* xr = x + (size_t)gw * NHID;
    float xv[24];
#pragma unroll
    for (int u = 0; u < 24; u++) xv[u] = xr[lane + (u << 5)];
    int b = gw >> 13;        // /8192
    int s = gw & (NS - 1);
    for (int h = 0; h < NH; h++) {
        const float* wr = lrw + h * NHID;
        float sum = 0.f;
#pragma unroll
        for (int u = 0; u < 24; u++) sum += xv[u] * wr[lane + (u << 5)];
        sum = warpAllSum(sum);
        if (lane == 0) {
            float zv = sum + lrb[h];
            g_eta[((size_t)b * NH + h) * NS + s] =
                (1.0f / (1.0f + expf(-zv))) * (1.0f / (float)ND);
        }
    }
}

// ------------ causal dwconv (taps s-4..s-1) + RoPE + transpose to [B,H,S,D] ---
__global__ __launch_bounds__(256) void conv_rope_kernel(
    const float* __restrict__ cqw, const float* __restrict__ cqb,
    const float* __restrict__ ckw, const float* __restrict__ ckb)
{
    int bh = blockIdx.y;
    int b = bh / NH, h = bh % NH;
    int s = blockIdx.x * 8 + (threadIdx.x >> 5);
    int p = threadIdx.x & 31;                  // rotation pair index
    int c0 = h * ND + 2 * p;

    float qe = cqb[c0], qo = cqb[c0 + 1];
    float ke = ckb[c0], ko = ckb[c0 + 1];
    const float* xb = g_xqk + ((size_t)b * NS) * NHID + c0;
#pragma unroll
    for (int kk = 0; kk < 4; kk++) {
        int ss = s + kk - 4;
        if (ss >= 0) {
            float2 xv2 = *(const float2*)(xb + (size_t)ss * NHID);
            float2 w1 = *(const float2*)(cqw + kk * NHID + c0);
            float2 w2 = *(const float2*)(ckw + kk * NHID + c0);
            qe += w1.x * xv2.x; qo += w1.y * xv2.y;
            ke += w2.x * xv2.x; ko += w2.y * xv2.y;
        }
    }
    // inv_freq computed in double (correctly rounded), angle rounded to f32
    // exactly like the reference's f32 s*inv_freq, sin/cos evaluated accurately.
    float ex = (float)(2 * p) / (float)ND;
    float invf = (float)exp(-(double)ex * 9.210340371976184);  // 10000^-ex
    float ang = (float)s * invf;
    double da = (double)ang;
    float sn = (float)sin(da), cn = (float)cos(da);

    float2 qO = make_float2(qe * cn - qo * sn, qe * sn + qo * cn);
    float2 kO = make_float2(ke * cn - ko * sn, ke * sn + ko * cn);
    size_t o = ((size_t)bh * NS + s) * ND + 2 * p;
    *(float2*)(g_xq + o) = qO;
    *(float2*)(g_xk + o) = kO;
    float2 vv = *(const float2*)(g_xvr + ((size_t)b * NS + s) * NHID + c0);
    *(float2*)(g_xv + o) = vv;
}

// ---------------- the sequential TTT scan: 48 blocks, 512 threads -------------
#define TP 68   // padded tile row stride (bank-conflict-free column access)
#define ZP 66   // padded Z scratch stride

__global__ __launch_bounds__(512) void scan_kernel(
    const float* __restrict__ lti, const float* __restrict__ tns,
    const float* __restrict__ tnb, const float* __restrict__ W1g,
    const float* __restrict__ b1g)
{
    __shared__ float W1s[ND * ND];
    __shared__ float b1s[ND], gsc[ND], gbi[ND];
    __shared__ float qs[NK * TP], ks[NK * TP], vs[NK * TP], grs[NK * TP];
    __shared__ float ztmp[NK * ZP];
    __shared__ float coef[NK][17];
    __shared__ float etav[NK], tk[NK];

    int bh = blockIdx.x;
    int b = bh / NH, h = bh % NH;
    int tid = threadIdx.x;
    int w = tid >> 5, lane = tid & 31;

    for (int i = tid; i < ND * ND; i += 512) W1s[i] = W1g[h * ND * ND + i];
    if (tid < ND) {
        b1s[tid] = b1g[h * ND + tid];
        gsc[tid] = tns[h * ND + tid];
        gbi[tid] = tnb[h * ND + tid];
    }
    if (tid < NK) tk[tid] = fmaxf(1.0f / (float)(tid + 1) + lti[tid], 0.0f);

    const float* qg = g_xq + (size_t)bh * NS * ND;
    const float* kg = g_xk + (size_t)bh * NS * ND;
    const float* vg = g_xv + (size_t)bh * NS * ND;
    const float* eg = g_eta + (size_t)bh * NS;
    float* zg = g_Z + (size_t)b * NS * NHID + h * ND;

    // column-group mapping: warp w owns cols [4w,4w+4); lane -> (row r2, col pair)
    int r2 = lane >> 1;
    int cA = (w << 2) + ((lane & 1) << 1);
    // row mapping: warp w owns row w; lane -> cols (lane, lane+32)
    int c0 = lane, c1 = lane + 32;
    __syncthreads();

    for (int mb = 0; mb < NMB; mb++) {
        // ---- load q,k,v minibatch tiles (contiguous 1024 floats each) ----
        for (int idx = tid; idx < 768; idx += 512) {
            int t = idx >> 8, e = idx & 255;
            const float* src = (t == 0 ? qg : (t == 1 ? kg : vg)) +
                               (size_t)mb * (NK * ND) + (e << 2);
            float* dst = (t == 0 ? qs : (t == 1 ? ks : vs)) +
                         (e >> 4) * TP + ((e & 15) << 2);
            *(float4*)dst = *(const float4*)src;
        }
        if (tid < NK) etav[tid] = eg[mb * NK + tid];
        __syncthreads();

        // ---- phase 2: Z1 = k @ W1 + b1 (column-group) ----
        {
            float z0 = b1s[cA], z1 = b1s[cA + 1];
            const float* kr = ks + r2 * TP;
#pragma unroll 8
            for (int d = 0; d < ND; d++) {
                float kd = kr[d];
                float2 wv = *(const float2*)&W1s[d * ND + cA];
                z0 += kd * wv.x; z1 += kd * wv.y;
            }
            ztmp[r2 * ZP + cA] = z0;
            ztmp[r2 * ZP + cA + 1] = z1;
        }
        __syncthreads();

        // ---- phase 3 (row): LN-L2 backward -> grad ; Attn row + coef ----
        {
            float z0 = ztmp[w * ZP + c0], z1 = ztmp[w * ZP + c1];
            float mu = warpAllSum(z0 + z1) * (1.f / 64.f);
            float var = warpAllSum(z0 * z0 + z1 * z1) * (1.f / 64.f) - mu * mu;
            float rstd = rsqrtf(var + 1e-5f);
            float xh0 = (z0 - mu) * rstd, xh1 = (z1 - mu) * rstd;
            float g0 = gsc[c0], g1 = gsc[c1];
            float t0 = vs[w * TP + c0] - ks[w * TP + c0];
            float t1 = vs[w * TP + c1] - ks[w * TP + c1];
            float gx0 = (xh0 * g0 + gbi[c0] - t0) * g0;
            float gx1 = (xh1 * g1 + gbi[c1] - t1) * g1;
            float m1 = warpAllSum(gx0 + gx1) * (1.f / 64.f);
            float m2 = warpAllSum(gx0 * xh0 + gx1 * xh1) * (1.f / 64.f);
            grs[w * TP + c0] = (gx0 - m1 - xh0 * m2) * rstd;
            grs[w * TP + c1] = (gx1 - m1 - xh1 * m2) * rstd;

            if (lane < NK) {   // Attn[w][j] ; coef = eta*(Attn+1) for j<=w
                int j = lane;
                float a = 0.f;
                const float* qr = qs + w * TP;
                const float* kj = ks + j * TP;
#pragma unroll 8
                for (int d = 0; d < ND; d++) a += qr[d] * kj[d];
                coef[w][j] = (j <= w) ? tk[w] * etav[j] * (a + 1.0f) : 0.0f;
            }
        }
        __syncthreads();

        // ---- phase 4: Z1_bar = q@W1 + b1 - sum_j coef*grad_j (column-group) --
        {
            float z0 = b1s[cA], z1 = b1s[cA + 1];
            const float* qr = qs + r2 * TP;
#pragma unroll 8
            for (int d = 0; d < ND; d++) {
                float qd = qr[d];
                float2 wv = *(const float2*)&W1s[d * ND + cA];
                z0 += qd * wv.x; z1 += qd * wv.y;
            }
#pragma unroll
            for (int j = 0; j < NK; j++) {
                float co = coef[r2][j];
                float2 gv = *(const float2*)&grs[j * TP + cA];
                z0 -= co * gv.x; z1 -= co * gv.y;
            }
            ztmp[r2 * ZP + cA] = z0;
            ztmp[r2 * ZP + cA + 1] = z1;
        }
        __syncthreads();

        // ---- phase 5 (row): out = q + ln_fwd(Z1_bar) ; then W1/b1 update ----
        {
            float z0 = ztmp[w * ZP + c0], z1 = ztmp[w * ZP + c1];
            float mu = warpAllSum(z0 + z1) * (1.f / 64.f);
            float var = warpAllSum(z0 * z0 + z1 * z1) * (1.f / 64.f) - mu * mu;
            float rstd = rsqrtf(var + 1e-5f);
            int s = mb * NK + w;
            float* orow = zg + (size_t)s * NHID;
            orow[c0] = qs[w * TP + c0] + (z0 - mu) * rstd * gsc[c0] + gbi[c0];
            orow[c1] = qs[w * TP + c1] + (z1 - mu) * rstd * gsc[c1] + gbi[c1];
        }
        {
            float lc = tk[NK - 1];
            int dd = tid >> 3;
            int e0 = (tid & 7) << 3;
            float acc[8] = {0, 0, 0, 0, 0, 0, 0, 0};
#pragma unroll
            for (int j = 0; j < NK; j++) {
                float lk = lc * etav[j] * ks[j * TP + dd];
                const float* gj = grs + j * TP + e0;
#pragma unroll
                for (int u = 0; u < 8; u++) acc[u] += lk * gj[u];
            }
            float* wr = W1s + dd * ND + e0;
#pragma unroll
            for (int u = 0; u < 8; u++) wr[u] -= acc[u];
            if (tid < ND) {
                float a = 0.f;
#pragma unroll
                for (int j = 0; j < NK; j++) a += etav[j] * grs[j * TP + tid];
                b1s[tid] -= lc * a;
            }
        }
        __syncthreads();
    }
}

// -------- post-norm over 768 + gelu(gate) product, writes G (reuses g_xqk) ----
__global__ __launch_bounds__(256) void postnorm_kernel(
    const float* __restrict__ pns, const float* __restrict__ pnb)
{
    int t = blockIdx.x;
    int tid = threadIdx.x;
    const float* zr = g_Z + (size_t)t * NHID;
    const float* gr = g_gate + (size_t)t * NHID;
    float* orow = g_xqk + (size_t)t * NHID;

    float z0 = zr[tid], z1 = zr[tid + 256], z2 = zr[tid + 512];
    float s1 = warpAllSum(z0 + z1 + z2);
    float s2 = warpAllSum(z0 * z0 + z1 * z1 + z2 * z2);
    __shared__ float sm1[8], sm2[8];
    if ((tid & 31) == 0) { sm1[tid >> 5] = s1; sm2[tid >> 5] = s2; }
    __syncthreads();
    float T1 = 0.f, T2 = 0.f;
#pragma unroll
    for (int i = 0; i < 8; i++) { T1 += sm1[i]; T2 += sm2[i]; }
    float mu = T1 * (1.f / 768.f);
    float var = T2 * (1.f / 768.f) - mu * mu;
    float rstd = rsqrtf(var + 1e-5f);
#pragma unroll
    for (int u = 0; u < 3; u++) {
        int c = tid + (u << 8);
        float zz = (u == 0 ? z0 : (u == 1 ? z1 : z2));
        float zn = (zz - mu) * rstd * pns[c] + pnb[c];
        float gv = gr[c];
        float g3 = 0.5f * gv *
                   (1.f + tanhf(0.7978845608028654f * (gv + 0.044715f * gv * gv * gv)));
        orow[c] = zn * g3;
    }
}

// ------------------------------- launcher ------------------------------------
extern "C" void kernel_launch(void* const* d_in, const int* in_sizes, int n_in,
                              void* d_out, int out_size)
{
    const float* x   = (const float*)d_in[0];
    const float* wq  = (const float*)d_in[1];
    const float* wv  = (const float*)d_in[2];
    const float* wo  = (const float*)d_in[3];
    const float* wg  = (const float*)d_in[4];
    const float* cqw = (const float*)d_in[5];
    const float* cqb = (const float*)d_in[6];
    const float* ckw = (const float*)d_in[7];
    const float* ckb = (const float*)d_in[8];
    const float* lrw = (const float*)d_in[9];
    const float* lrb = (const float*)d_in[10];
    const float* lti = (const float*)d_in[11];
    const float* tns = (const float*)d_in[12];
    const float* tnb = (const float*)d_in[13];
    const float* pns = (const float*)d_in[14];
    const float* pnb = (const float*)d_in[15];
    const float* W1  = (const float*)d_in[16];
    const float* b1  = (const float*)d_in[17];
    float* out = (float*)d_out;

    float *p_xqk, *p_xvr, *p_gate;
    cudaGetSymbolAddress((void**)&p_xqk, g_xqk);
    cudaGetSymbolAddress((void**)&p_xvr, g_xvr);
    cudaGetSymbolAddress((void**)&p_gate, g_gate);

    dim3 gg(NHID / 128, NTOK / 128);   // (6, 256)

    sgemm128<<<gg, 256>>>(x, wq, p_xqk, NTOK, NHID, NHID);
    sgemm128<<<gg, 256>>>(x, wv, p_xvr, NTOK, NHID, NHID);
    sgemm128<<<gg, 256>>>(x, wg, p_gate, NTOK, NHID, NHID);
    lr_kernel<<<(NTOK * 32) / 256, 256>>>(x, lrw, lrb);
    conv_rope_kernel<<<dim3(NS / 8, NB * NH), 256>>>(cqw, cqb, ckw, ckb);
    scan_kernel<<<NB * NH, 512>>>(lti, tns, tnb, W1, b1);
    postnorm_kernel<<<NTOK, 256>>>(pns, pnb);
    sgemm128<<<gg, 256>>>(p_xqk /*G*/, wo, out, NTOK, NHID, NHID);
}

// round 3
// speedup vs baseline: 1.4052x; 1.4052x over previous
#include <cuda_runtime.h>
#include <cuda_bf16.h>
#include <math.h>
#include <stdint.h>

// Problem constants
#define NB 4
#define NS 8192
#define NHID 768
#define NH 12
#define ND 64
#define NK 16
#define NMB (NS/NK)          // 512
#define NTOK (NB*NS)         // 32768
#define KSP 2304             // split-K (3 x 768)
#define NCH 36               // K chunks of 64

// ---------------- scratch (device globals; no allocs allowed) ----------------
__device__ __nv_bfloat16 g_asplit[(size_t)NTOK*KSP]; // split A (x, later G)
__device__ float g_qvg[(size_t)NTOK*KSP];            // fused q|v|gate output f32
__device__ __nv_bfloat16 g_bt1[(size_t)KSP*KSP];     // Bt for qvg gemm [N=2304,K=2304]
__device__ __nv_bfloat16 g_bt2[(size_t)NHID*KSP];    // Bt for wo gemm  [N=768, K=2304]
__device__ float g_xq[(size_t)NTOK*NHID];            // [B,H,S,D]
__device__ float g_xk[(size_t)NTOK*NHID];
__device__ float g_xv[(size_t)NTOK*NHID];
__device__ float g_Z[(size_t)NTOK*NHID];             // scan output [B,S,H*D]
__device__ float g_eta[NB*NH*NS];

__device__ __forceinline__ float warpAllSum(float v) {
#pragma unroll
    for (int o = 16; o; o >>= 1) v += __shfl_xor_sync(0xffffffffu, v, o);
    return v;
}

__device__ __forceinline__ uint32_t smem_u32(const void* p) {
    uint32_t a;
    asm("{ .reg .u64 t; cvta.to.shared.u64 t, %1; cvt.u32.u64 %0, t; }"
        : "=r"(a) : "l"(p));
    return a;
}

#define CPA16(sa, gp) \
    asm volatile("cp.async.cg.shared.global [%0], [%1], 16;" \
        :: "r"(sa), "l"(__cvta_generic_to_global(gp)) : "memory")
#define CPA_COMMIT() asm volatile("cp.async.commit_group;" ::: "memory")
#define CPA_WAIT2()  asm volatile("cp.async.wait_group 2;" ::: "memory")

__device__ __forceinline__ void ldsm4(uint32_t* r, uint32_t a) {
    asm volatile("ldmatrix.sync.aligned.m8n8.x4.shared.b16 {%0,%1,%2,%3}, [%4];"
        : "=r"(r[0]), "=r"(r[1]), "=r"(r[2]), "=r"(r[3]) : "r"(a));
}
__device__ __forceinline__ void mma16816(float* c, const uint32_t* a,
                                         const uint32_t* b) {
    asm volatile("mma.sync.aligned.m16n8k16.row.col.f32.bf16.bf16.f32 "
        "{%0,%1,%2,%3}, {%4,%5,%6,%7}, {%8,%9}, {%0,%1,%2,%3};"
        : "+f"(c[0]), "+f"(c[1]), "+f"(c[2]), "+f"(c[3])
        : "r"(a[0]), "r"(a[1]), "r"(a[2]), "r"(a[3]), "r"(b[0]), "r"(b[1]));
}

// ======================= mma.sync GEMM: C = A * Bt^T ==========================
// A [M, 2304] bf16 row-major, Bt [N, 2304] bf16 row-major, C [M, ldc] f32
// grid = (N/128, M/128), 256 threads (8 warps, each 64x32). K fixed = 2304.
#define STAGE_BYTES 16384
__global__ __launch_bounds__(256) void mma_gemm(
    const __nv_bfloat16* __restrict__ A, const __nv_bfloat16* __restrict__ Bt,
    float* __restrict__ C, int ldc)
{
    extern __shared__ char dsm[];
    uint32_t sbase = (smem_u32(dsm) + 1023u) & ~1023u;
    uint32_t aS = sbase;                    // 3 A stages
    uint32_t bS = sbase + 3 * STAGE_BYTES;  // 3 B stages

    int tid = threadIdx.x, lane = tid & 31, w = tid >> 5;
    int m0 = blockIdx.y * 128, n0 = blockIdx.x * 128;
    int mw = (w & 1) * 64, nw = (w >> 1) * 32;

    // cp.async coords: 4 rows per pass (r0 + 32t), 16B col group cg
    int r0 = tid >> 3, cg = tid & 7;
    uint32_t st_off = (uint32_t)(r0 * 128 + ((cg * 16) ^ ((r0 & 7) << 4)));
    const __nv_bfloat16* ga = A  + (size_t)(m0 + r0) * KSP + cg * 8;
    const __nv_bfloat16* gb = Bt + (size_t)(n0 + r0) * KSP + cg * 8;

    // prologue: chunks 0..2
#pragma unroll
    for (int j = 0; j < 3; j++) {
#pragma unroll
        for (int t = 0; t < 4; t++) {
            CPA16(aS + j * STAGE_BYTES + st_off + t * 4096,
                  ga + (size_t)t * 32 * KSP + j * 64);
            CPA16(bS + j * STAGE_BYTES + st_off + t * 4096,
                  gb + (size_t)t * 32 * KSP + j * 64);
        }
        CPA_COMMIT();
    }

    // ldmatrix base offsets (swizzle bits depend only on lane&7)
    uint32_t swz = (uint32_t)((lane & 7) << 4);
    uint32_t a_row_byte = (uint32_t)((mw + (lane & 15)) * 128);
    uint32_t a_khalf = (uint32_t)((lane >> 4) * 16);
    uint32_t b_row_byte = (uint32_t)((nw + (lane & 7) + ((lane >> 4) << 3)) * 128);
    uint32_t b_khalf = (uint32_t)(((lane >> 3) & 1) * 16);

    float cacc[4][4][4];
#pragma unroll
    for (int i = 0; i < 4; i++)
#pragma unroll
        for (int j = 0; j < 4; j++)
#pragma unroll
            for (int k = 0; k < 4; k++) cacc[i][j][k] = 0.f;

    for (int i = 0; i < NCH; i++) {
        int si = i % 3;
        CPA_WAIT2();
        __syncthreads();
        uint32_t aT = aS + si * STAGE_BYTES;
        uint32_t bT = bS + si * STAGE_BYTES;
#pragma unroll
        for (int ks = 0; ks < 4; ks++) {
            uint32_t afr[4][4], bfr[4][2];
#pragma unroll
            for (int am = 0; am < 4; am++) {
                uint32_t row_b = a_row_byte + am * (16 * 128);
                ldsm4(afr[am], aT + row_b + ((ks * 32 + a_khalf) ^ swz));
            }
#pragma unroll
            for (int bg = 0; bg < 2; bg++) {
                uint32_t t4[4];
                uint32_t row_b = b_row_byte + bg * (16 * 128);
                ldsm4(t4, bT + row_b + ((ks * 32 + b_khalf) ^ swz));
                bfr[bg * 2 + 0][0] = t4[0]; bfr[bg * 2 + 0][1] = t4[1];
                bfr[bg * 2 + 1][0] = t4[2]; bfr[bg * 2 + 1][1] = t4[3];
            }
#pragma unroll
            for (int am = 0; am < 4; am++)
#pragma unroll
                for (int bn = 0; bn < 4; bn++)
                    mma16816(cacc[am][bn], afr[am], bfr[bn]);
        }
        __syncthreads();
        int jn = i + 3;
        if (jn < NCH) {
#pragma unroll
            for (int t = 0; t < 4; t++) {
                CPA16(aS + si * STAGE_BYTES + st_off + t * 4096,
                      ga + (size_t)t * 32 * KSP + jn * 64);
                CPA16(bS + si * STAGE_BYTES + st_off + t * 4096,
                      gb + (size_t)t * 32 * KSP + jn * 64);
            }
        }
        CPA_COMMIT();
    }

    // epilogue: c frag thread t: rows m+t/4, m+t/4+8 ; cols n+(t%4)*2+{0,1}
    int erow = lane >> 2, ecol = (lane & 3) * 2;
#pragma unroll
    for (int am = 0; am < 4; am++) {
#pragma unroll
        for (int bn = 0; bn < 4; bn++) {
            int r = m0 + mw + am * 16 + erow;
            int c = n0 + nw + bn * 8 + ecol;
            *(float2*)&C[(size_t)r * ldc + c] =
                make_float2(cacc[am][bn][0], cacc[am][bn][1]);
            *(float2*)&C[(size_t)(r + 8) * ldc + c] =
                make_float2(cacc[am][bn][2], cacc[am][bn][3]);
        }
    }
}

// ---------------- conversion: x -> split bf16 [Ah|Al|Ah] ----------------------
__global__ __launch_bounds__(256) void split_x_kernel(const float* __restrict__ x)
{
    size_t t = blockIdx.x;
    __nv_bfloat16* dst = g_asplit + t * KSP;
    const float* src = x + t * NHID;
#pragma unroll
    for (int u = 0; u < 3; u++) {
        int cidx = threadIdx.x + (u << 8);
        float v = src[cidx];
        __nv_bfloat16 hi = __float2bfloat16(v);
        __nv_bfloat16 lo = __float2bfloat16(v - __bfloat162float(hi));
        dst[cidx] = hi;
        dst[NHID + cidx] = lo;
        dst[2 * NHID + cidx] = hi;
    }
}

// ---------------- build transposed split weights [Bh|Bh|Bl] -------------------
__global__ __launch_bounds__(256) void build_bt_kernel(
    __nv_bfloat16* __restrict__ dst, const float* __restrict__ w0,
    const float* __restrict__ w1, const float* __restrict__ w2)
{
    int np = blockIdx.x;                 // output column index n'
    int sel = np / NHID;
    const float* w = (sel == 0) ? w0 : (sel == 1) ? w1 : w2;
    int n = np % NHID;
    __nv_bfloat16* d = dst + (size_t)np * KSP;
#pragma unroll
    for (int u = 0; u < 3; u++) {
        int k = threadIdx.x + (u << 8);
        float v = w[(size_t)k * NHID + n];
        __nv_bfloat16 hi = __float2bfloat16(v);
        __nv_bfloat16 lo = __float2bfloat16(v - __bfloat162float(hi));
        d[k] = hi;
        d[NHID + k] = hi;
        d[2 * NHID + k] = lo;
    }
}

// ---------------- ttt_lr_eta = sigmoid(x . lr_w[h] + lr_b[h]) / D -------------
__global__ __launch_bounds__(256) void lr_kernel(
    const float* __restrict__ x, const float* __restrict__ lrw,
    const float* __restrict__ lrb)
{
    int gw = (blockIdx.x * blockDim.x + threadIdx.x) >> 5;
    int lane = threadIdx.x & 31;
    const float* xr = x + (size_t)gw * NHID;
    float xv[24];
#pragma unroll
    for (int u = 0; u < 24; u++) xv[u] = xr[lane + (u << 5)];
    int b = gw >> 13;
    int s = gw & (NS - 1);
    for (int h = 0; h < NH; h++) {
        const float* wr = lrw + h * NHID;
        float sum = 0.f;
#pragma unroll
        for (int u = 0; u < 24; u++) sum += xv[u] * wr[lane + (u << 5)];
        sum = warpAllSum(sum);
        if (lane == 0) {
            float zv = sum + lrb[h];
            g_eta[((size_t)b * NH + h) * NS + s] =
                (1.0f / (1.0f + expf(-zv))) * (1.0f / (float)ND);
        }
    }
}

// ------------ causal dwconv + RoPE + transpose to [B,H,S,D] -------------------
__global__ __launch_bounds__(256) void conv_rope_kernel(
    const float* __restrict__ cqw, const float* __restrict__ cqb,
    const float* __restrict__ ckw, const float* __restrict__ ckb)
{
    int bh = blockIdx.y;
    int b = bh / NH, h = bh % NH;
    int s = blockIdx.x * 8 + (threadIdx.x >> 5);
    int p = threadIdx.x & 31;
    int c0 = h * ND + 2 * p;

    float qe = cqb[c0], qo = cqb[c0 + 1];
    float ke = ckb[c0], ko = ckb[c0 + 1];
    const float* xb = g_qvg + ((size_t)b * NS) * KSP + c0;   // q part, cols 0..767
#pragma unroll
    for (int kk = 0; kk < 4; kk++) {
        int ss = s + kk - 4;
        if (ss >= 0) {
            float2 xv2 = *(const float2*)(xb + (size_t)ss * KSP);
            float2 w1 = *(const float2*)(cqw + kk * NHID + c0);
            float2 w2 = *(const float2*)(ckw + kk * NHID + c0);
            qe += w1.x * xv2.x; qo += w1.y * xv2.y;
            ke += w2.x * xv2.x; ko += w2.y * xv2.y;
        }
    }
    float ex = (float)(2 * p) / (float)ND;
    float invf = (float)exp(-(double)ex * 9.210340371976184);
    float ang = (float)s * invf;
    double da = (double)ang;
    float sn = (float)sin(da), cn = (float)cos(da);

    float2 qO = make_float2(qe * cn - qo * sn, qe * sn + qo * cn);
    float2 kO = make_float2(ke * cn - ko * sn, ke * sn + ko * cn);
    size_t o = ((size_t)bh * NS + s) * ND + 2 * p;
    *(float2*)(g_xq + o) = qO;
    *(float2*)(g_xk + o) = kO;
    float2 vv = *(const float2*)(g_qvg + ((size_t)b * NS + s) * KSP + NHID + c0);
    *(float2*)(g_xv + o) = vv;
}

// ---------------- the sequential TTT scan: 48 blocks, 512 threads -------------
#define TP 68
#define ZP 66

__global__ __launch_bounds__(512) void scan_kernel(
    const float* __restrict__ lti, const float* __restrict__ tns,
    const float* __restrict__ tnb, const float* __restrict__ W1g,
    const float* __restrict__ b1g)
{
    __shared__ float W1s[ND * ND];
    __shared__ float b1s[ND], gsc[ND], gbi[ND];
    __shared__ float qs[NK * TP], ks[NK * TP], vs[NK * TP], grs[NK * TP];
    __shared__ float ztmp[NK * ZP];
    __shared__ float coef[NK][17];
    __shared__ float etav[NK], tk[NK];

    int bh = blockIdx.x;
    int b = bh / NH, h = bh % NH;
    int tid = threadIdx.x;
    int w = tid >> 5, lane = tid & 31;

    for (int i = tid; i < ND * ND; i += 512) W1s[i] = W1g[h * ND * ND + i];
    if (tid < ND) {
        b1s[tid] = b1g[h * ND + tid];
        gsc[tid] = tns[h * ND + tid];
        gbi[tid] = tnb[h * ND + tid];
    }
    if (tid < NK) tk[tid] = fmaxf(1.0f / (float)(tid + 1) + lti[tid], 0.0f);

    const float* qg = g_xq + (size_t)bh * NS * ND;
    const float* kg = g_xk + (size_t)bh * NS * ND;
    const float* vg = g_xv + (size_t)bh * NS * ND;
    const float* eg = g_eta + (size_t)bh * NS;
    float* zg = g_Z + (size_t)b * NS * NHID + h * ND;

    int r2 = lane >> 1;
    int cA = (w << 2) + ((lane & 1) << 1);
    int c0 = lane, c1 = lane + 32;
    __syncthreads();

    for (int mb = 0; mb < NMB; mb++) {
        for (int idx = tid; idx < 768; idx += 512) {
            int t = idx >> 8, e = idx & 255;
            const float* src = (t == 0 ? qg : (t == 1 ? kg : vg)) +
                               (size_t)mb * (NK * ND) + (e << 2);
            float* dst = (t == 0 ? qs : (t == 1 ? ks : vs)) +
                         (e >> 4) * TP + ((e & 15) << 2);
            *(float4*)dst = *(const float4*)src;
        }
        if (tid < NK) etav[tid] = eg[mb * NK + tid];
        __syncthreads();

        {
            float z0 = b1s[cA], z1 = b1s[cA + 1];
            const float* kr = ks + r2 * TP;
#pragma unroll 8
            for (int d = 0; d < ND; d++) {
                float kd = kr[d];
                float2 wv = *(const float2*)&W1s[d * ND + cA];
                z0 += kd * wv.x; z1 += kd * wv.y;
            }
            ztmp[r2 * ZP + cA] = z0;
            ztmp[r2 * ZP + cA + 1] = z1;
        }
        __syncthreads();

        {
            float z0 = ztmp[w * ZP + c0], z1 = ztmp[w * ZP + c1];
            float mu = warpAllSum(z0 + z1) * (1.f / 64.f);
            float var = warpAllSum(z0 * z0 + z1 * z1) * (1.f / 64.f) - mu * mu;
            float rstd = rsqrtf(var + 1e-5f);
            float xh0 = (z0 - mu) * rstd, xh1 = (z1 - mu) * rstd;
            float g0 = gsc[c0], g1 = gsc[c1];
            float t0 = vs[w * TP + c0] - ks[w * TP + c0];
            float t1 = vs[w * TP + c1] - ks[w * TP + c1];
            float gx0 = (xh0 * g0 + gbi[c0] - t0) * g0;
            float gx1 = (xh1 * g1 + gbi[c1] - t1) * g1;
            float m1 = warpAllSum(gx0 + gx1) * (1.f / 64.f);
            float m2 = warpAllSum(gx0 * xh0 + gx1 * xh1) * (1.f / 64.f);
            grs[w * TP + c0] = (gx0 - m1 - xh0 * m2) * rstd;
            grs[w * TP + c1] = (gx1 - m1 - xh1 * m2) * rstd;

            if (lane < NK) {
                int j = lane;
                float a = 0.f;
                const float* qr = qs + w * TP;
                const float* kj = ks + j * TP;
#pragma unroll 8
                for (int d = 0; d < ND; d++) a += qr[d] * kj[d];
                coef[w][j] = (j <= w) ? tk[w] * etav[j] * (a + 1.0f) : 0.0f;
            }
        }
        __syncthreads();

        {
            float z0 = b1s[cA], z1 = b1s[cA + 1];
            const float* qr = qs + r2 * TP;
#pragma unroll 8
            for (int d = 0; d < ND; d++) {
                float qd = qr[d];
                float2 wv = *(const float2*)&W1s[d * ND + cA];
                z0 += qd * wv.x; z1 += qd * wv.y;
            }
#pragma unroll
            for (int j = 0; j < NK; j++) {
                float co = coef[r2][j];
                float2 gv = *(const float2*)&grs[j * TP + cA];
                z0 -= co * gv.x; z1 -= co * gv.y;
            }
            ztmp[r2 * ZP + cA] = z0;
            ztmp[r2 * ZP + cA + 1] = z1;
        }
        __syncthreads();

        {
            float z0 = ztmp[w * ZP + c0], z1 = ztmp[w * ZP + c1];
            float mu = warpAllSum(z0 + z1) * (1.f / 64.f);
            float var = warpAllSum(z0 * z0 + z1 * z1) * (1.f / 64.f) - mu * mu;
            float rstd = rsqrtf(var + 1e-5f);
            int s = mb * NK + w;
            float* orow = zg + (size_t)s * NHID;
            orow[c0] = qs[w * TP + c0] + (z0 - mu) * rstd * gsc[c0] + gbi[c0];
            orow[c1] = qs[w * TP + c1] + (z1 - mu) * rstd * gsc[c1] + gbi[c1];
        }
        {
            float lc = tk[NK - 1];
            int dd = tid >> 3;
            int e0 = (tid & 7) << 3;
            float acc[8] = {0, 0, 0, 0, 0, 0, 0, 0};
#pragma unroll
            for (int j = 0; j < NK; j++) {
                float lk = lc * etav[j] * ks[j * TP + dd];
                const float* gj = grs + j * TP + e0;
#pragma unroll
                for (int u = 0; u < 8; u++) acc[u] += lk * gj[u];
            }
            float* wr = W1s + dd * ND + e0;
#pragma unroll
            for (int u = 0; u < 8; u++) wr[u] -= acc[u];
            if (tid < ND) {
                float a = 0.f;
#pragma unroll
                for (int j = 0; j < NK; j++) a += etav[j] * grs[j * TP + tid];
                b1s[tid] -= lc * a;
            }
        }
        __syncthreads();
    }
}

// -------- post-norm + gelu(gate) product, writes split-bf16 G -----------------
__global__ __launch_bounds__(256) void postnorm_kernel(
    const float* __restrict__ pns, const float* __restrict__ pnb)
{
    int t = blockIdx.x;
    int tid = threadIdx.x;
    const float* zr = g_Z + (size_t)t * NHID;
    const float* gr = g_qvg + (size_t)t * KSP + 2 * NHID;   // gate part
    __nv_bfloat16* orow = g_asplit + (size_t)t * KSP;

    float z0 = zr[tid], z1 = zr[tid + 256], z2 = zr[tid + 512];
    float s1 = warpAllSum(z0 + z1 + z2);
    float s2 = warpAllSum(z0 * z0 + z1 * z1 + z2 * z2);
    __shared__ float sm1[8], sm2[8];
    if ((tid & 31) == 0) { sm1[tid >> 5] = s1; sm2[tid >> 5] = s2; }
    __syncthreads();
    float T1 = 0.f, T2 = 0.f;
#pragma unroll
    for (int i = 0; i < 8; i++) { T1 += sm1[i]; T2 += sm2[i]; }
    float mu = T1 * (1.f / 768.f);
    float var = T2 * (1.f / 768.f) - mu * mu;
    float rstd = rsqrtf(var + 1e-5f);
#pragma unroll
    for (int u = 0; u < 3; u++) {
        int cidx = tid + (u << 8);
        float zz = (u == 0 ? z0 : (u == 1 ? z1 : z2));
        float zn = (zz - mu) * rstd * pns[cidx] + pnb[cidx];
        float gv = gr[cidx];
        float g3 = 0.5f * gv *
                   (1.f + tanhf(0.7978845608028654f * (gv + 0.044715f * gv * gv * gv)));
        float val = zn * g3;
        __nv_bfloat16 hi = __float2bfloat16(val);
        __nv_bfloat16 lo = __float2bfloat16(val - __bfloat162float(hi));
        orow[cidx] = hi;
        orow[NHID + cidx] = lo;
        orow[2 * NHID + cidx] = hi;
    }
}

// ------------------------------- launcher ------------------------------------
#define GEMM_DSM (1024 + 6 * STAGE_BYTES)

extern "C" void kernel_launch(void* const* d_in, const int* in_sizes, int n_in,
                              void* d_out, int out_size)
{
    const float* x   = (const float*)d_in[0];
    const float* wq  = (const float*)d_in[1];
    const float* wv  = (const float*)d_in[2];
    const float* wo  = (const float*)d_in[3];
    const float* wg  = (const float*)d_in[4];
    const float* cqw = (const float*)d_in[5];
    const float* cqb = (const float*)d_in[6];
    const float* ckw = (const float*)d_in[7];
    const float* ckb = (const float*)d_in[8];
    const float* lrw = (const float*)d_in[9];
    const float* lrb = (const float*)d_in[10];
    const float* lti = (const float*)d_in[11];
    const float* tns = (const float*)d_in[12];
    const float* tnb = (const float*)d_in[13];
    const float* pns = (const float*)d_in[14];
    const float* pnb = (const float*)d_in[15];
    const float* W1  = (const float*)d_in[16];
    const float* b1  = (const float*)d_in[17];
    float* out = (float*)d_out;

    __nv_bfloat16 *p_asplit, *p_bt1, *p_bt2;
    float *p_qvg;
    cudaGetSymbolAddress((void**)&p_asplit, g_asplit);
    cudaGetSymbolAddress((void**)&p_bt1, g_bt1);
    cudaGetSymbolAddress((void**)&p_bt2, g_bt2);
    cudaGetSymbolAddress((void**)&p_qvg, g_qvg);

    cudaFuncSetAttribute(mma_gemm, cudaFuncAttributeMaxDynamicSharedMemorySize,
                         GEMM_DSM);

    split_x_kernel<<<NTOK, 256>>>(x);
    build_bt_kernel<<<KSP, 256>>>(p_bt1, wq, wv, wg);
    build_bt_kernel<<<NHID, 256>>>(p_bt2, wo, wo, wo);

    mma_gemm<<<dim3(KSP / 128, NTOK / 128), 256, GEMM_DSM>>>(p_asplit, p_bt1,
                                                             p_qvg, KSP);

    lr_kernel<<<(NTOK * 32) / 256, 256>>>(x, lrw, lrb);
    conv_rope_kernel<<<dim3(NS / 8, NB * NH), 256>>>(cqw, cqb, ckw, ckb);
    scan_kernel<<<NB * NH, 512>>>(lti, tns, tnb, W1, b1);
    postnorm_kernel<<<NTOK, 256>>>(pns, pnb);

    mma_gemm<<<dim3(NHID / 128, NTOK / 128), 256, GEMM_DSM>>>(p_asplit, p_bt2,
                                                              out, NHID);
}

// round 5
// speedup vs baseline: 1.4069x; 1.0012x over previous
#include <cuda_runtime.h>
#include <cuda_bf16.h>
#include <math.h>
#include <stdint.h>

// Problem constants
#define NB 4
#define NS 8192
#define NHID 768
#define NH 12
#define ND 64
#define NK 16
#define NMB (NS/NK)          // 512
#define NTOK (NB*NS)         // 32768
#define KSP 2304             // split-K (3 x 768)
#define NCH 36               // K chunks of 64

// ---------------- scratch (device globals; no allocs allowed) ----------------
__device__ __nv_bfloat16 g_asplit[(size_t)NTOK*KSP]; // split A (x, later G)
__device__ float g_qvg[(size_t)NTOK*KSP];            // fused q|v|gate output f32
__device__ __nv_bfloat16 g_bt1[(size_t)KSP*KSP];     // Bt for qvg gemm [N=2304,K=2304]
__device__ __nv_bfloat16 g_bt2[(size_t)NHID*KSP];    // Bt for wo gemm  [N=768, K=2304]
__device__ float g_xq[(size_t)NTOK*NHID];            // [B,H,S,D]
__device__ float g_xk[(size_t)NTOK*NHID];
__device__ float g_xv[(size_t)NTOK*NHID];
__device__ float g_Z[(size_t)NTOK*NHID];             // scan output [B,S,H*D]
__device__ float g_eta[NB*NH*NS];

__device__ __forceinline__ float warpAllSum(float v) {
#pragma unroll
    for (int o = 16; o; o >>= 1) v += __shfl_xor_sync(0xffffffffu, v, o);
    return v;
}

__device__ __forceinline__ uint32_t smem_u32(const void* p) {
    uint32_t a;
    asm("{ .reg .u64 t; cvta.to.shared.u64 t, %1; cvt.u32.u64 %0, t; }"
        : "=r"(a) : "l"(p));
    return a;
}

#define CPA16(sa, gp) \
    asm volatile("cp.async.cg.shared.global [%0], [%1], 16;" \
        :: "r"(sa), "l"(__cvta_generic_to_global(gp)) : "memory")
#define CPA_COMMIT() asm volatile("cp.async.commit_group;" ::: "memory")
#define CPA_WAIT2()  asm volatile("cp.async.wait_group 2;" ::: "memory")

__device__ __forceinline__ void ldsm4(uint32_t* r, uint32_t a) {
    asm volatile("ldmatrix.sync.aligned.m8n8.x4.shared.b16 {%0,%1,%2,%3}, [%4];"
        : "=r"(r[0]), "=r"(r[1]), "=r"(r[2]), "=r"(r[3]) : "r"(a));
}
__device__ __forceinline__ void mma16816(float* c, const uint32_t* a,
                                         const uint32_t* b) {
    asm volatile("mma.sync.aligned.m16n8k16.row.col.f32.bf16.bf16.f32 "
        "{%0,%1,%2,%3}, {%4,%5,%6,%7}, {%8,%9}, {%0,%1,%2,%3};"
        : "+f"(c[0]), "+f"(c[1]), "+f"(c[2]), "+f"(c[3])
        : "r"(a[0]), "r"(a[1]), "r"(a[2]), "r"(a[3]), "r"(b[0]), "r"(b[1]));
}

// ======================= mma.sync GEMM: C = A * Bt^T ==========================
// A [M, 2304] bf16 row-major, Bt [N, 2304] bf16 row-major, C [M, ldc] f32
// grid = (N/128, M/128), 256 threads (8 warps, each 64x32). K fixed = 2304.
#define STAGE_BYTES 16384
__global__ __launch_bounds__(256) void mma_gemm(
    const __nv_bfloat16* __restrict__ A, const __nv_bfloat16* __restrict__ Bt,
    float* __restrict__ C, int ldc)
{
    extern __shared__ char dsm[];
    uint32_t sbase = (smem_u32(dsm) + 1023u) & ~1023u;
    uint32_t aS = sbase;                    // 3 A stages
    uint32_t bS = sbase + 3 * STAGE_BYTES;  // 3 B stages

    int tid = threadIdx.x, lane = tid & 31, w = tid >> 5;
    int m0 = blockIdx.y * 128, n0 = blockIdx.x * 128;
    int mw = (w & 1) * 64, nw = (w >> 1) * 32;

    // cp.async coords: 4 rows per pass (r0 + 32t), 16B col group cg
    int r0 = tid >> 3, cg = tid & 7;
    uint32_t st_off = (uint32_t)(r0 * 128 + ((cg * 16) ^ ((r0 & 7) << 4)));
    const __nv_bfloat16* ga = A  + (size_t)(m0 + r0) * KSP + cg * 8;
    const __nv_bfloat16* gb = Bt + (size_t)(n0 + r0) * KSP + cg * 8;

    // prologue: chunks 0..2
#pragma unroll
    for (int j = 0; j < 3; j++) {
#pragma unroll
        for (int t = 0; t < 4; t++) {
            CPA16(aS + j * STAGE_BYTES + st_off + t * 4096,
                  ga + (size_t)t * 32 * KSP + j * 64);
            CPA16(bS + j * STAGE_BYTES + st_off + t * 4096,
                  gb + (size_t)t * 32 * KSP + j * 64);
        }
        CPA_COMMIT();
    }

    // ldmatrix base offsets (swizzle bits depend only on lane&7)
    uint32_t swz = (uint32_t)((lane & 7) << 4);
    uint32_t a_row_byte = (uint32_t)((mw + (lane & 15)) * 128);
    uint32_t a_khalf = (uint32_t)((lane >> 4) * 16);
    uint32_t b_row_byte = (uint32_t)((nw + (lane & 7) + ((lane >> 4) << 3)) * 128);
    uint32_t b_khalf = (uint32_t)(((lane >> 3) & 1) * 16);

    float cacc[4][4][4];
#pragma unroll
    for (int i = 0; i < 4; i++)
#pragma unroll
        for (int j = 0; j < 4; j++)
#pragma unroll
            for (int k = 0; k < 4; k++) cacc[i][j][k] = 0.f;

    for (int i = 0; i < NCH; i++) {
        int si = i % 3;
        CPA_WAIT2();
        __syncthreads();
        uint32_t aT = aS + si * STAGE_BYTES;
        uint32_t bT = bS + si * STAGE_BYTES;
#pragma unroll
        for (int ks = 0; ks < 4; ks++) {
            uint32_t afr[4][4], bfr[4][2];
#pragma unroll
            for (int am = 0; am < 4; am++) {
                uint32_t row_b = a_row_byte + am * (16 * 128);
                ldsm4(afr[am], aT + row_b + ((ks * 32 + a_khalf) ^ swz));
            }
#pragma unroll
            for (int bg = 0; bg < 2; bg++) {
                uint32_t t4[4];
                uint32_t row_b = b_row_byte + bg * (16 * 128);
                ldsm4(t4, bT + row_b + ((ks * 32 + b_khalf) ^ swz));
                bfr[bg * 2 + 0][0] = t4[0]; bfr[bg * 2 + 0][1] = t4[1];
                bfr[bg * 2 + 1][0] = t4[2]; bfr[bg * 2 + 1][1] = t4[3];
            }
#pragma unroll
            for (int am = 0; am < 4; am++)
#pragma unroll
                for (int bn = 0; bn < 4; bn++)
                    mma16816(cacc[am][bn], afr[am], bfr[bn]);
        }
        __syncthreads();
        int jn = i + 3;
        if (jn < NCH) {
#pragma unroll
            for (int t = 0; t < 4; t++) {
                CPA16(aS + si * STAGE_BYTES + st_off + t * 4096,
                      ga + (size_t)t * 32 * KSP + jn * 64);
                CPA16(bS + si * STAGE_BYTES + st_off + t * 4096,
                      gb + (size_t)t * 32 * KSP + jn * 64);
            }
        }
        CPA_COMMIT();
    }

    // epilogue: c frag thread t: rows m+t/4, m+t/4+8 ; cols n+(t%4)*2+{0,1}
    int erow = lane >> 2, ecol = (lane & 3) * 2;
#pragma unroll
    for (int am = 0; am < 4; am++) {
#pragma unroll
        for (int bn = 0; bn < 4; bn++) {
            int r = m0 + mw + am * 16 + erow;
            int c = n0 + nw + bn * 8 + ecol;
            *(float2*)&C[(size_t)r * ldc + c] =
                make_float2(cacc[am][bn][0], cacc[am][bn][1]);
            *(float2*)&C[(size_t)(r + 8) * ldc + c] =
                make_float2(cacc[am][bn][2], cacc[am][bn][3]);
        }
    }
}

// ---------------- conversion: x -> split bf16 [Ah|Al|Ah] ----------------------
__global__ __launch_bounds__(256) void split_x_kernel(const float* __restrict__ x)
{
    size_t t = blockIdx.x;
    __nv_bfloat16* dst = g_asplit + t * KSP;
    const float* src = x + t * NHID;
#pragma unroll
    for (int u = 0; u < 3; u++) {
        int cidx = threadIdx.x + (u << 8);
        float v = src[cidx];
        __nv_bfloat16 hi = __float2bfloat16(v);
        __nv_bfloat16 lo = __float2bfloat16(v - __bfloat162float(hi));
        dst[cidx] = hi;
        dst[NHID + cidx] = lo;
        dst[2 * NHID + cidx] = hi;
    }
}

// ---------------- build transposed split weights [Bh|Bh|Bl] -------------------
__global__ __launch_bounds__(256) void build_bt_kernel(
    __nv_bfloat16* __restrict__ dst, const float* __restrict__ w0,
    const float* __restrict__ w1, const float* __restrict__ w2)
{
    int np = blockIdx.x;                 // output column index n'
    int sel = np / NHID;
    const float* w = (sel == 0) ? w0 : (sel == 1) ? w1 : w2;
    int n = np % NHID;
    __nv_bfloat16* d = dst + (size_t)np * KSP;
#pragma unroll
    for (int u = 0; u < 3; u++) {
        int k = threadIdx.x + (u << 8);
        float v = w[(size_t)k * NHID + n];
        __nv_bfloat16 hi = __float2bfloat16(v);
        __nv_bfloat16 lo = __float2bfloat16(v - __bfloat162float(hi));
        d[k] = hi;
        d[NHID + k] = hi;
        d[2 * NHID + k] = lo;
    }
}

// ---------------- ttt_lr_eta = sigmoid(x . lr_w[h] + lr_b[h]) / D -------------
__global__ __launch_bounds__(256) void lr_kernel(
    const float* __restrict__ x, const float* __restrict__ lrw,
    const float* __restrict__ lrb)
{
    int gw = (blockIdx.x * blockDim.x + threadIdx.x) >> 5;
    int lane = threadIdx.x & 31;
    const float* xr = x + (size_t)gw * NHID;
    float xv[24];
#pragma unroll
    for (int u = 0; u < 24; u++) xv[u] = xr[lane + (u << 5)];
    int b = gw >> 13;
    int s = gw & (NS - 1);
    for (int h = 0; h < NH; h++) {
        const float* wr = lrw + h * NHID;
        float sum = 0.f;
#pragma unroll
        for (int u = 0; u < 24; u++) sum += xv[u] * wr[lane + (u << 5)];
        sum = warpAllSum(sum);
        if (lane == 0) {
            float zv = sum + lrb[h];
            g_eta[((size_t)b * NH + h) * NS + s] =
                (1.0f / (1.0f + expf(-zv))) * (1.0f / (float)ND);
        }
    }
}

// ------------ causal dwconv + RoPE + transpose to [B,H,S,D] -------------------
__global__ __launch_bounds__(256) void conv_rope_kernel(
    const float* __restrict__ cqw, const float* __restrict__ cqb,
    const float* __restrict__ ckw, const float* __restrict__ ckb)
{
    int bh = blockIdx.y;
    int b = bh / NH, h = bh % NH;
    int s = blockIdx.x * 8 + (threadIdx.x >> 5);
    int p = threadIdx.x & 31;
    int c0 = h * ND + 2 * p;

    float qe = cqb[c0], qo = cqb[c0 + 1];
    float ke = ckb[c0], ko = ckb[c0 + 1];
    const float* xb = g_qvg + ((size_t)b * NS) * KSP + c0;   // q part, cols 0..767
#pragma unroll
    for (int kk = 0; kk < 4; kk++) {
        int ss = s + kk - 4;
        if (ss >= 0) {
            float2 xv2 = *(const float2*)(xb + (size_t)ss * KSP);
            float2 w1 = *(const float2*)(cqw + kk * NHID + c0);
            float2 w2 = *(const float2*)(ckw + kk * NHID + c0);
            qe += w1.x * xv2.x; qo += w1.y * xv2.y;
            ke += w2.x * xv2.x; ko += w2.y * xv2.y;
        }
    }
    float ex = (float)(2 * p) / (float)ND;
    float invf = (float)exp(-(double)ex * 9.210340371976184);
    float ang = (float)s * invf;
    double da = (double)ang;
    float sn = (float)sin(da), cn = (float)cos(da);

    float2 qO = make_float2(qe * cn - qo * sn, qe * sn + qo * cn);
    float2 kO = make_float2(ke * cn - ko * sn, ke * sn + ko * cn);
    size_t o = ((size_t)bh * NS + s) * ND + 2 * p;
    *(float2*)(g_xq + o) = qO;
    *(float2*)(g_xk + o) = kO;
    float2 vv = *(const float2*)(g_qvg + ((size_t)b * NS + s) * KSP + NHID + c0);
    *(float2*)(g_xv + o) = vv;
}

// ---------------- the sequential TTT scan: 48 blocks, 512 threads -------------
#define TP 68
#define ZP 66

__global__ __launch_bounds__(512) void scan_kernel(
    const float* __restrict__ lti, const float* __restrict__ tns,
    const float* __restrict__ tnb, const float* __restrict__ W1g,
    const float* __restrict__ b1g)
{
    __shared__ float W1s[ND * ND];
    __shared__ float b1s[ND], gsc[ND], gbi[ND];
    __shared__ float qs[NK * TP], ks[NK * TP], vs[NK * TP], grs[NK * TP];
    __shared__ float ztmp[NK * ZP];
    __shared__ float coef[NK][17];
    __shared__ float etav[NK], tk[NK];

    int bh = blockIdx.x;
    int b = bh / NH, h = bh % NH;
    int tid = threadIdx.x;
    int w = tid >> 5, lane = tid & 31;

    for (int i = tid; i < ND * ND; i += 512) W1s[i] = W1g[h * ND * ND + i];
    if (tid < ND) {
        b1s[tid] = b1g[h * ND + tid];
        gsc[tid] = tns[h * ND + tid];
        gbi[tid] = tnb[h * ND + tid];
    }
    if (tid < NK) tk[tid] = fmaxf(1.0f / (float)(tid + 1) + lti[tid], 0.0f);

    const float* qg = g_xq + (size_t)bh * NS * ND;
    const float* kg = g_xk + (size_t)bh * NS * ND;
    const float* vg = g_xv + (size_t)bh * NS * ND;
    const float* eg = g_eta + (size_t)bh * NS;
    float* zg = g_Z + (size_t)b * NS * NHID + h * ND;

    int r2 = lane >> 1;
    int cA = (w << 2) + ((lane & 1) << 1);
    int c0 = lane, c1 = lane + 32;
    __syncthreads();

    for (int mb = 0; mb < NMB; mb++) {
        for (int idx = tid; idx < 768; idx += 512) {
            int t = idx >> 8, e = idx & 255;
            const float* src = (t == 0 ? qg : (t == 1 ? kg : vg)) +
                               (size_t)mb * (NK * ND) + (e << 2);
            float* dst = (t == 0 ? qs : (t == 1 ? ks : vs)) +
                         (e >> 4) * TP + ((e & 15) << 2);
            *(float4*)dst = *(const float4*)src;
        }
        if (tid < NK) etav[tid] = eg[mb * NK + tid];
        __syncthreads();

        {
            float z0 = b1s[cA], z1 = b1s[cA + 1];
            const float* kr = ks + r2 * TP;
#pragma unroll 8
            for (int d = 0; d < ND; d++) {
                float kd = kr[d];
                float2 wv = *(const float2*)&W1s[d * ND + cA];
                z0 += kd * wv.x; z1 += kd * wv.y;
            }
            ztmp[r2 * ZP + cA] = z0;
            ztmp[r2 * ZP + cA + 1] = z1;
        }
        __syncthreads();

        {
            float z0 = ztmp[w * ZP + c0], z1 = ztmp[w * ZP + c1];
            float mu = warpAllSum(z0 + z1) * (1.f / 64.f);
            float var = warpAllSum(z0 * z0 + z1 * z1) * (1.f / 64.f) - mu * mu;
            float rstd = rsqrtf(var + 1e-5f);
            float xh0 = (z0 - mu) * rstd, xh1 = (z1 - mu) * rstd;
            float g0 = gsc[c0], g1 = gsc[c1];
            float t0 = vs[w * TP + c0] - ks[w * TP + c0];
            float t1 = vs[w * TP + c1] - ks[w * TP + c1];
            float gx0 = (xh0 * g0 + gbi[c0] - t0) * g0;
            float gx1 = (xh1 * g1 + gbi[c1] - t1) * g1;
            float m1 = warpAllSum(gx0 + gx1) * (1.f / 64.f);
            float m2 = warpAllSum(gx0 * xh0 + gx1 * xh1) * (1.f / 64.f);
            grs[w * TP + c0] = (gx0 - m1 - xh0 * m2) * rstd;
            grs[w * TP + c1] = (gx1 - m1 - xh1 * m2) * rstd;

            if (lane < NK) {
                int j = lane;
                float a = 0.f;
                const float* qr = qs + w * TP;
                const float* kj = ks + j * TP;
#pragma unroll 8
                for (int d = 0; d < ND; d++) a += qr[d] * kj[d];
                coef[w][j] = (j <= w) ? tk[w] * etav[j] * (a + 1.0f) : 0.0f;
            }
        }
        __syncthreads();

        {
            float z0 = b1s[cA], z1 = b1s[cA + 1];
            const float* qr = qs + r2 * TP;
#pragma unroll 8
            for (int d = 0; d < ND; d++) {
                float qd = qr[d];
                float2 wv = *(const float2*)&W1s[d * ND + cA];
                z0 += qd * wv.x; z1 += qd * wv.y;
            }
#pragma unroll
            for (int j = 0; j < NK; j++) {
                float co = coef[r2][j];
                float2 gv = *(const float2*)&grs[j * TP + cA];
                z0 -= co * gv.x; z1 -= co * gv.y;
            }
            ztmp[r2 * ZP + cA] = z0;
            ztmp[r2 * ZP + cA + 1] = z1;
        }
        __syncthreads();

        {
            float z0 = ztmp[w * ZP + c0], z1 = ztmp[w * ZP + c1];
            float mu = warpAllSum(z0 + z1) * (1.f / 64.f);
            float var = warpAllSum(z0 * z0 + z1 * z1) * (1.f / 64.f) - mu * mu;
            float rstd = rsqrtf(var + 1e-5f);
            int s = mb * NK + w;
            float* orow = zg + (size_t)s * NHID;
            orow[c0] = qs[w * TP + c0] + (z0 - mu) * rstd * gsc[c0] + gbi[c0];
            orow[c1] = qs[w * TP + c1] + (z1 - mu) * rstd * gsc[c1] + gbi[c1];
        }
        {
            float lc = tk[NK - 1];
            int dd = tid >> 3;
            int e0 = (tid & 7) << 3;
            float acc[8] = {0, 0, 0, 0, 0, 0, 0, 0};
#pragma unroll
            for (int j = 0; j < NK; j++) {
                float lk = lc * etav[j] * ks[j * TP + dd];
                const float* gj = grs + j * TP + e0;
#pragma unroll
                for (int u = 0; u < 8; u++) acc[u] += lk * gj[u];
            }
            float* wr = W1s + dd * ND + e0;
#pragma unroll
            for (int u = 0; u < 8; u++) wr[u] -= acc[u];
            if (tid < ND) {
                float a = 0.f;
#pragma unroll
                for (int j = 0; j < NK; j++) a += etav[j] * grs[j * TP + tid];
                b1s[tid] -= lc * a;
            }
        }
        __syncthreads();
    }
}

// -------- post-norm + gelu(gate) product, writes split-bf16 G -----------------
__global__ __launch_bounds__(256) void postnorm_kernel(
    const float* __restrict__ pns, const float* __restrict__ pnb)
{
    int t = blockIdx.x;
    int tid = threadIdx.x;
    const float* zr = g_Z + (size_t)t * NHID;
    const float* gr = g_qvg + (size_t)t * KSP + 2 * NHID;   // gate part
    __nv_bfloat16* orow = g_asplit + (size_t)t * KSP;

    float z0 = zr[tid], z1 = zr[tid + 256], z2 = zr[tid + 512];
    float s1 = warpAllSum(z0 + z1 + z2);
    float s2 = warpAllSum(z0 * z0 + z1 * z1 + z2 * z2);
    __shared__ float sm1[8], sm2[8];
    if ((tid & 31) == 0) { sm1[tid >> 5] = s1; sm2[tid >> 5] = s2; }
    __syncthreads();
    float T1 = 0.f, T2 = 0.f;
#pragma unroll
    for (int i = 0; i < 8; i++) { T1 += sm1[i]; T2 += sm2[i]; }
    float mu = T1 * (1.f / 768.f);
    float var = T2 * (1.f / 768.f) - mu * mu;
    float rstd = rsqrtf(var + 1e-5f);
#pragma unroll
    for (int u = 0; u < 3; u++) {
        int cidx = tid + (u << 8);
        float zz = (u == 0 ? z0 : (u == 1 ? z1 : z2));
        float zn = (zz - mu) * rstd * pns[cidx] + pnb[cidx];
        float gv = gr[cidx];
        float g3 = 0.5f * gv *
                   (1.f + tanhf(0.7978845608028654f * (gv + 0.044715f * gv * gv * gv)));
        float val = zn * g3;
        __nv_bfloat16 hi = __float2bfloat16(val);
        __nv_bfloat16 lo = __float2bfloat16(val - __bfloat162float(hi));
        orow[cidx] = hi;
        orow[NHID + cidx] = lo;
        orow[2 * NHID + cidx] = hi;
    }
}

// ------------------------------- launcher ------------------------------------
#define GEMM_DSM (1024 + 6 * STAGE_BYTES)

extern "C" void kernel_launch(void* const* d_in, const int* in_sizes, int n_in,
                              void* d_out, int out_size)
{
    const float* x   = (const float*)d_in[0];
    const float* wq  = (const float*)d_in[1];
    const float* wv  = (const float*)d_in[2];
    const float* wo  = (const float*)d_in[3];
    const float* wg  = (const float*)d_in[4];
    const float* cqw = (const float*)d_in[5];
    const float* cqb = (const float*)d_in[6];
    const float* ckw = (const float*)d_in[7];
    const float* ckb = (const float*)d_in[8];
    const float* lrw = (const float*)d_in[9];
    const float* lrb = (const float*)d_in[10];
    const float* lti = (const float*)d_in[11];
    const float* tns = (const float*)d_in[12];
    const float* tnb = (const float*)d_in[13];
    const float* pns = (const float*)d_in[14];
    const float* pnb = (const float*)d_in[15];
    const float* W1  = (const float*)d_in[16];
    const float* b1  = (const float*)d_in[17];
    float* out = (float*)d_out;

    __nv_bfloat16 *p_asplit, *p_bt1, *p_bt2;
    float *p_qvg;
    cudaGetSymbolAddress((void**)&p_asplit, g_asplit);
    cudaGetSymbolAddress((void**)&p_bt1, g_bt1);
    cudaGetSymbolAddress((void**)&p_bt2, g_bt2);
    cudaGetSymbolAddress((void**)&p_qvg, g_qvg);

    cudaFuncSetAttribute(mma_gemm, cudaFuncAttributeMaxDynamicSharedMemorySize,
                         GEMM_DSM);

    split_x_kernel<<<NTOK, 256>>>(x);
    build_bt_kernel<<<KSP, 256>>>(p_bt1, wq, wv, wg);
    build_bt_kernel<<<NHID, 256>>>(p_bt2, wo, wo, wo);

    mma_gemm<<<dim3(KSP / 128, NTOK / 128), 256, GEMM_DSM>>>(p_asplit, p_bt1,
                                                             p_qvg, KSP);

    lr_kernel<<<(NTOK * 32) / 256, 256>>>(x, lrw, lrb);
    conv_rope_kernel<<<dim3(NS / 8, NB * NH), 256>>>(cqw, cqb, ckw, ckb);
    scan_kernel<<<NB * NH, 512>>>(lti, tns, tnb, W1, b1);
    postnorm_kernel<<<NTOK, 256>>>(pns, pnb);

    mma_gemm<<<dim3(NHID / 128, NTOK / 128), 256, GEMM_DSM>>>(p_asplit, p_bt2,
                                                              out, NHID);
}

// round 6
// speedup vs baseline: 1.5990x; 1.1365x over previous
#include <cuda_runtime.h>
#include <cuda_bf16.h>
#include <math.h>
#include <stdint.h>

// Problem constants
#define NB 4
#define NS 8192
#define NHID 768
#define NH 12
#define ND 64
#define NK 16
#define NMB (NS/NK)          // 512
#define NTOK (NB*NS)         // 32768
#define KSP 2304             // split-K (3 x 768)
#define NCH 36               // K chunks of 64

// ---------------- scratch (device globals; no allocs allowed) ----------------
__device__ __nv_bfloat16 g_asplit[(size_t)NTOK*KSP]; // split A (x, later G)
__device__ float g_qvg[(size_t)NTOK*KSP];            // fused q|v|gate output f32
__device__ __nv_bfloat16 g_bt1[(size_t)KSP*KSP];     // Bt for qvg gemm
__device__ __nv_bfloat16 g_bt2[(size_t)NHID*KSP];    // Bt for wo gemm
__device__ float g_xq[(size_t)NTOK*NHID];            // [B,H, mb, d, r] col-major tiles
__device__ float g_xk[(size_t)NTOK*NHID];
__device__ float g_xv[(size_t)NTOK*NHID];
__device__ float g_Z[(size_t)NTOK*NHID];             // scan output [B,S,H*D]
__device__ float g_eta[NB*NH*NS];

__device__ __forceinline__ float warpAllSum(float v) {
#pragma unroll
    for (int o = 16; o; o >>= 1) v += __shfl_xor_sync(0xffffffffu, v, o);
    return v;
}

__device__ __forceinline__ uint32_t smem_u32(const void* p) {
    uint32_t a;
    asm("{ .reg .u64 t; cvta.to.shared.u64 t, %1; cvt.u32.u64 %0, t; }"
        : "=r"(a) : "l"(p));
    return a;
}

#define CPA16(sa, gp) \
    asm volatile("cp.async.cg.shared.global [%0], [%1], 16;" \
        :: "r"(sa), "l"(__cvta_generic_to_global(gp)) : "memory")
#define CPA_COMMIT() asm volatile("cp.async.commit_group;" ::: "memory")
#define CPA_WAIT2()  asm volatile("cp.async.wait_group 2;" ::: "memory")
#define CPA_WAIT1()  asm volatile("cp.async.wait_group 1;" ::: "memory")

__device__ __forceinline__ void ldsm4(uint32_t* r, uint32_t a) {
    asm volatile("ldmatrix.sync.aligned.m8n8.x4.shared.b16 {%0,%1,%2,%3}, [%4];"
        : "=r"(r[0]), "=r"(r[1]), "=r"(r[2]), "=r"(r[3]) : "r"(a));
}
__device__ __forceinline__ void mma16816(float* c, const uint32_t* a,
                                         const uint32_t* b) {
    asm volatile("mma.sync.aligned.m16n8k16.row.col.f32.bf16.bf16.f32 "
        "{%0,%1,%2,%3}, {%4,%5,%6,%7}, {%8,%9}, {%0,%1,%2,%3};"
        : "+f"(c[0]), "+f"(c[1]), "+f"(c[2]), "+f"(c[3])
        : "r"(a[0]), "r"(a[1]), "r"(a[2]), "r"(a[3]), "r"(b[0]), "r"(b[1]));
}

// ======================= mma.sync GEMM: C = A * Bt^T ==========================
#define STAGE_BYTES 16384
__global__ __launch_bounds__(256) void mma_gemm(
    const __nv_bfloat16* __restrict__ A, const __nv_bfloat16* __restrict__ Bt,
    float* __restrict__ C, int ldc)
{
    extern __shared__ char dsm[];
    uint32_t sbase = (smem_u32(dsm) + 1023u) & ~1023u;
    uint32_t aS = sbase;
    uint32_t bS = sbase + 3 * STAGE_BYTES;

    int tid = threadIdx.x, lane = tid & 31, w = tid >> 5;
    int m0 = blockIdx.y * 128, n0 = blockIdx.x * 128;
    int mw = (w & 1) * 64, nw = (w >> 1) * 32;

    int r0 = tid >> 3, cg = tid & 7;
    uint32_t st_off = (uint32_t)(r0 * 128 + ((cg * 16) ^ ((r0 & 7) << 4)));
    const __nv_bfloat16* ga = A  + (size_t)(m0 + r0) * KSP + cg * 8;
    const __nv_bfloat16* gb = Bt + (size_t)(n0 + r0) * KSP + cg * 8;

#pragma unroll
    for (int j = 0; j < 3; j++) {
#pragma unroll
        for (int t = 0; t < 4; t++) {
            CPA16(aS + j * STAGE_BYTES + st_off + t * 4096,
                  ga + (size_t)t * 32 * KSP + j * 64);
            CPA16(bS + j * STAGE_BYTES + st_off + t * 4096,
                  gb + (size_t)t * 32 * KSP + j * 64);
        }
        CPA_COMMIT();
    }

    uint32_t swz = (uint32_t)((lane & 7) << 4);
    uint32_t a_row_byte = (uint32_t)((mw + (lane & 15)) * 128);
    uint32_t a_khalf = (uint32_t)((lane >> 4) * 16);
    uint32_t b_row_byte = (uint32_t)((nw + (lane & 7) + ((lane >> 4) << 3)) * 128);
    uint32_t b_khalf = (uint32_t)(((lane >> 3) & 1) * 16);

    float cacc[4][4][4];
#pragma unroll
    for (int i = 0; i < 4; i++)
#pragma unroll
        for (int j = 0; j < 4; j++)
#pragma unroll
            for (int k = 0; k < 4; k++) cacc[i][j][k] = 0.f;

    for (int i = 0; i < NCH; i++) {
        int si = i % 3;
        CPA_WAIT2();
        __syncthreads();
        uint32_t aT = aS + si * STAGE_BYTES;
        uint32_t bT = bS + si * STAGE_BYTES;
#pragma unroll
        for (int ks = 0; ks < 4; ks++) {
            uint32_t afr[4][4], bfr[4][2];
#pragma unroll
            for (int am = 0; am < 4; am++) {
                uint32_t row_b = a_row_byte + am * (16 * 128);
                ldsm4(afr[am], aT + row_b + ((ks * 32 + a_khalf) ^ swz));
            }
#pragma unroll
            for (int bg = 0; bg < 2; bg++) {
                uint32_t t4[4];
                uint32_t row_b = b_row_byte + bg * (16 * 128);
                ldsm4(t4, bT + row_b + ((ks * 32 + b_khalf) ^ swz));
                bfr[bg * 2 + 0][0] = t4[0]; bfr[bg * 2 + 0][1] = t4[1];
                bfr[bg * 2 + 1][0] = t4[2]; bfr[bg * 2 + 1][1] = t4[3];
            }
#pragma unroll
            for (int am = 0; am < 4; am++)
#pragma unroll
                for (int bn = 0; bn < 4; bn++)
                    mma16816(cacc[am][bn], afr[am], bfr[bn]);
        }
        __syncthreads();
        int jn = i + 3;
        if (jn < NCH) {
#pragma unroll
            for (int t = 0; t < 4; t++) {
                CPA16(aS + si * STAGE_BYTES + st_off + t * 4096,
                      ga + (size_t)t * 32 * KSP + jn * 64);
                CPA16(bS + si * STAGE_BYTES + st_off + t * 4096,
                      gb + (size_t)t * 32 * KSP + jn * 64);
            }
        }
        CPA_COMMIT();
    }

    int erow = lane >> 2, ecol = (lane & 3) * 2;
#pragma unroll
    for (int am = 0; am < 4; am++) {
#pragma unroll
        for (int bn = 0; bn < 4; bn++) {
            int r = m0 + mw + am * 16 + erow;
            int c = n0 + nw + bn * 8 + ecol;
            *(float2*)&C[(size_t)r * ldc + c] =
                make_float2(cacc[am][bn][0], cacc[am][bn][1]);
            *(float2*)&C[(size_t)(r + 8) * ldc + c] =
                make_float2(cacc[am][bn][2], cacc[am][bn][3]);
        }
    }
}

// ---------------- conversion: x -> split bf16 [Ah|Al|Ah] ----------------------
__global__ __launch_bounds__(256) void split_x_kernel(const float* __restrict__ x)
{
    size_t t = blockIdx.x;
    __nv_bfloat16* dst = g_asplit + t * KSP;
    const float* src = x + t * NHID;
#pragma unroll
    for (int u = 0; u < 3; u++) {
        int cidx = threadIdx.x + (u << 8);
        float v = src[cidx];
        __nv_bfloat16 hi = __float2bfloat16(v);
        __nv_bfloat16 lo = __float2bfloat16(v - __bfloat162float(hi));
        dst[cidx] = hi;
        dst[NHID + cidx] = lo;
        dst[2 * NHID + cidx] = hi;
    }
}

// ---------------- build transposed split weights [Bh|Bh|Bl] -------------------
__global__ __launch_bounds__(256) void build_bt_kernel(
    __nv_bfloat16* __restrict__ dst, const float* __restrict__ w0,
    const float* __restrict__ w1, const float* __restrict__ w2)
{
    int np = blockIdx.x;
    int sel = np / NHID;
    const float* w = (sel == 0) ? w0 : (sel == 1) ? w1 : w2;
    int n = np % NHID;
    __nv_bfloat16* d = dst + (size_t)np * KSP;
#pragma unroll
    for (int u = 0; u < 3; u++) {
        int k = threadIdx.x + (u << 8);
        float v = w[(size_t)k * NHID + n];
        __nv_bfloat16 hi = __float2bfloat16(v);
        __nv_bfloat16 lo = __float2bfloat16(v - __bfloat162float(hi));
        d[k] = hi;
        d[NHID + k] = hi;
        d[2 * NHID + k] = lo;
    }
}

// ---------------- ttt_lr_eta = sigmoid(x . lr_w[h] + lr_b[h]) / D -------------
__global__ __launch_bounds__(256) void lr_kernel(
    const float* __restrict__ x, const float* __restrict__ lrw,
    const float* __restrict__ lrb)
{
    int gw = (blockIdx.x * blockDim.x + threadIdx.x) >> 5;
    int lane = threadIdx.x & 31;
    const float* xr = x + (size_t)gw * NHID;
    float xv[24];
#pragma unroll
    for (int u = 0; u < 24; u++) xv[u] = xr[lane + (u << 5)];
    int b = gw >> 13;
    int s = gw & (NS - 1);
    for (int h = 0; h < NH; h++) {
        const float* wr = lrw + h * NHID;
        float sum = 0.f;
#pragma unroll
        for (int u = 0; u < 24; u++) sum += xv[u] * wr[lane + (u << 5)];
        sum = warpAllSum(sum);
        if (lane == 0) {
            float zv = sum + lrb[h];
            g_eta[((size_t)b * NH + h) * NS + s] =
                (1.0f / (1.0f + expf(-zv))) * (1.0f / (float)ND);
        }
    }
}

// ------------ causal dwconv + RoPE + transposed [bh][mb][d][r] output ---------
__global__ __launch_bounds__(256) void conv_rope_kernel(
    const float* __restrict__ cqw, const float* __restrict__ cqb,
    const float* __restrict__ ckw, const float* __restrict__ ckb)
{
    int bh = blockIdx.y;
    int b = bh / NH, h = bh % NH;
    int s = blockIdx.x * 8 + (threadIdx.x >> 5);
    int p = threadIdx.x & 31;
    int c0 = h * ND + 2 * p;

    float qe = cqb[c0], qo = cqb[c0 + 1];
    float ke = ckb[c0], ko = ckb[c0 + 1];
    const float* xb = g_qvg + ((size_t)b * NS) * KSP + c0;   // q part
#pragma unroll
    for (int kk = 0; kk < 4; kk++) {
        int ss = s + kk - 4;
        if (ss >= 0) {
            float2 xv2 = *(const float2*)(xb + (size_t)ss * KSP);
            float2 w1 = *(const float2*)(cqw + kk * NHID + c0);
            float2 w2 = *(const float2*)(ckw + kk * NHID + c0);
            qe += w1.x * xv2.x; qo += w1.y * xv2.y;
            ke += w2.x * xv2.x; ko += w2.y * xv2.y;
        }
    }
    float ex = (float)(2 * p) / (float)ND;
    float invf = (float)exp(-(double)ex * 9.210340371976184);
    float ang = (float)s * invf;
    double da = (double)ang;
    float sn = (float)sin(da), cn = (float)cos(da);

    float2 qO = make_float2(qe * cn - qo * sn, qe * sn + qo * cn);
    float2 kO = make_float2(ke * cn - ko * sn, ke * sn + ko * cn);
    float2 vv = *(const float2*)(g_qvg + ((size_t)b * NS + s) * KSP + NHID + c0);

    // transposed tile layout: [(bh*NMB + mb)*1024 + d*16 + r]
    size_t basep = ((size_t)bh * NMB + (s >> 4)) * 1024 + (s & 15);
    g_xq[basep + (2 * p) * 16]     = qO.x;
    g_xq[basep + (2 * p + 1) * 16] = qO.y;
    g_xk[basep + (2 * p) * 16]     = kO.x;
    g_xk[basep + (2 * p + 1) * 16] = kO.y;
    g_xv[basep + (2 * p) * 16]     = vv.x;
    g_xv[basep + (2 * p + 1) * 16] = vv.y;
}

// ---------------- the sequential TTT scan: 48 blocks, 512 threads -------------
// smem layout (floats), dynamic:
#define DP   20              // per-d stride of qkv tiles (16B aligned rows)
#define ARRF 1296            // per-array stride (bank offset 16 between q,k)
#define BUFF (3*ARRF)        // 3888 per buffer
#define W1P  68
#define OFF_W1   0           // 64*68
#define OFF_ZK   4352        // 16*68
#define OFF_ZQ   5440
#define OFF_GR   6528
#define OFF_COEF 7616        // 16*17
#define OFF_B1   7888
#define OFF_GSC  7952
#define OFF_GBI  8016
#define OFF_TK   8080
#define OFF_ETA  8096        // 2*16
#define OFF_QKV  8128
#define SCAN_SMEM_FLOATS (OFF_QKV + 2*BUFF)    // 15904
#define SCAN_DSM (SCAN_SMEM_FLOATS * 4)

__global__ __launch_bounds__(512) void scan_kernel(
    const float* __restrict__ lti, const float* __restrict__ tns,
    const float* __restrict__ tnb, const float* __restrict__ W1g,
    const float* __restrict__ b1g)
{
    extern __shared__ float S[];
    int bh = blockIdx.x;
    int b = bh / NH, h = bh % NH;
    int tid = threadIdx.x;
    int w = tid >> 5, lane = tid & 31;

    for (int i = tid; i < ND * ND; i += 512)
        S[OFF_W1 + (i >> 6) * W1P + (i & 63)] = W1g[h * ND * ND + i];
    if (tid < ND) {
        S[OFF_B1 + tid]  = b1g[h * ND + tid];
        S[OFF_GSC + tid] = tns[h * ND + tid];
        S[OFF_GBI + tid] = tnb[h * ND + tid];
    }
    if (tid < NK)
        S[OFF_TK + tid] = fmaxf(1.0f / (float)(tid + 1) + lti[tid], 0.0f);

    const float* gq = g_xq + (size_t)bh * (NMB * 1024);
    const float* gk = g_xk + (size_t)bh * (NMB * 1024);
    const float* gv = g_xv + (size_t)bh * (NMB * 1024);
    const float* eg = g_eta + (size_t)bh * NS;
    float* zg = g_Z + (size_t)b * NS * NHID + h * ND;

    uint32_t sbase = smem_u32(S);

    // prefetch for minibatch 0 into buffer 0
    for (int idx = tid; idx < 772; idx += 512) {
        if (idx < 768) {
            int arr = idx >> 8, rest = idx & 255, d = rest >> 2, ch = rest & 3;
            const float* src = (arr == 0 ? gq : (arr == 1 ? gk : gv)) +
                               d * 16 + ch * 4;
            CPA16(sbase + 4u * (OFF_QKV + arr * ARRF + d * DP + ch * 4), src);
        } else {
            int ch = idx - 768;
            CPA16(sbase + 4u * (OFF_ETA + ch * 4), eg + ch * 4);
        }
    }
    CPA_COMMIT();

    for (int mb = 0; mb < NMB; mb++) {
        int buf = mb & 1;
        // issue prefetch for mb+1 into other buffer
        if (mb + 1 < NMB) {
            int nb = buf ^ 1;
            size_t goff = (size_t)(mb + 1) * 1024;
            for (int idx = tid; idx < 772; idx += 512) {
                if (idx < 768) {
                    int arr = idx >> 8, rest = idx & 255, d = rest >> 2,
                        ch = rest & 3;
                    const float* src = (arr == 0 ? gq : (arr == 1 ? gk : gv)) +
                                       goff + d * 16 + ch * 4;
                    CPA16(sbase + 4u * (OFF_QKV + nb * BUFF + arr * ARRF +
                                        d * DP + ch * 4), src);
                } else {
                    int ch = idx - 768;
                    CPA16(sbase + 4u * (OFF_ETA + nb * 16 + ch * 4),
                          eg + (size_t)(mb + 1) * 16 + ch * 4);
                }
            }
        }
        CPA_COMMIT();
        CPA_WAIT1();
        __syncthreads();

        const float* QS = S + OFF_QKV + buf * BUFF;
        const float* KS = QS + ARRF;
        const float* VS = QS + 2 * ARRF;
        const float* ET = S + OFF_ETA + buf * 16;

        // ---- P1: merged Z1 = k@W1+b1 (half 0) and Z1q = q@W1+b1 (half 1) ----
        {
            int r = lane & 15, hf = lane >> 4, c4 = w << 2;
            const float* src = hf ? QS : KS;
            float a0 = S[OFF_B1 + c4],     a1 = S[OFF_B1 + c4 + 1];
            float a2 = S[OFF_B1 + c4 + 2], a3 = S[OFF_B1 + c4 + 3];
#pragma unroll 8
            for (int d = 0; d < ND; d++) {
                float4 wv = *(const float4*)&S[OFF_W1 + d * W1P + c4];
                float sv = src[d * DP + r];
                a0 += sv * wv.x; a1 += sv * wv.y;
                a2 += sv * wv.z; a3 += sv * wv.w;
            }
            float* dst = S + (hf ? OFF_ZQ : OFF_ZK) + r * W1P + c4;
            *(float4*)dst = make_float4(a0, a1, a2, a3);
        }
        __syncthreads();

        // ---- P2 (row w): LN-L2 backward -> grad ; full-warp attn + coef -----
        {
            int c0 = lane, c1 = lane + 32;
            float z0 = S[OFF_ZK + w * W1P + c0], z1 = S[OFF_ZK + w * W1P + c1];
            float mu = warpAllSum(z0 + z1) * (1.f / 64.f);
            float var = warpAllSum(z0 * z0 + z1 * z1) * (1.f / 64.f) - mu * mu;
            float rstd = rsqrtf(var + 1e-5f);
            float xh0 = (z0 - mu) * rstd, xh1 = (z1 - mu) * rstd;
            float g0 = S[OFF_GSC + c0], g1 = S[OFF_GSC + c1];
            float t0 = VS[c0 * DP + w] - KS[c0 * DP + w];
            float t1 = VS[c1 * DP + w] - KS[c1 * DP + w];
            float gx0 = (xh0 * g0 + S[OFF_GBI + c0] - t0) * g0;
            float gx1 = (xh1 * g1 + S[OFF_GBI + c1] - t1) * g1;
            float m1 = warpAllSum(gx0 + gx1) * (1.f / 64.f);
            float m2 = warpAllSum(gx0 * xh0 + gx1 * xh1) * (1.f / 64.f);
            S[OFF_GR + w * W1P + c0] = (gx0 - m1 - xh0 * m2) * rstd;
            S[OFF_GR + w * W1P + c1] = (gx1 - m1 - xh1 * m2) * rstd;

            int j = lane & 15, hf = lane >> 4;
            float a = 0.f;
#pragma unroll 8
            for (int dd = 0; dd < 32; dd++) {
                int d = (hf << 5) + dd;
                a += QS[d * DP + w] * KS[d * DP + j];
            }
            a += __shfl_xor_sync(0xffffffffu, a, 16);
            if (lane < NK)
                S[OFF_COEF + w * 17 + j] =
                    (j <= w) ? S[OFF_TK + w] * ET[j] * (a + 1.0f) : 0.0f;
        }
        __syncthreads();

        // ---- P3: Z1_bar corrections (col) + W1/b1 update ---------------------
        {
            int r = lane & 15, hf = lane >> 4, c2 = (w << 2) + (hf << 1);
            float z0 = S[OFF_ZQ + r * W1P + c2], z1 = S[OFF_ZQ + r * W1P + c2 + 1];
#pragma unroll
            for (int j = 0; j < NK; j++) {
                float co = S[OFF_COEF + r * 17 + j];
                float2 g2 = *(const float2*)&S[OFF_GR + j * W1P + c2];
                z0 -= co * g2.x; z1 -= co * g2.y;
            }
            S[OFF_ZQ + r * W1P + c2] = z0;
            S[OFF_ZQ + r * W1P + c2 + 1] = z1;
        }
        {
            float lc = S[OFF_TK + NK - 1];
            int dd = tid >> 3;
            int e0 = (tid & 7) << 3;
            float acc[8] = {0, 0, 0, 0, 0, 0, 0, 0};
#pragma unroll
            for (int j = 0; j < NK; j++) {
                float lk = lc * ET[j] * KS[dd * DP + j];
                const float* gj = &S[OFF_GR + j * W1P + e0];
#pragma unroll
                for (int u = 0; u < 8; u++) acc[u] += lk * gj[u];
            }
            float* wr = &S[OFF_W1 + dd * W1P + e0];
#pragma unroll
            for (int u = 0; u < 8; u++) wr[u] -= acc[u];
            if (tid < ND) {
                float a = 0.f;
#pragma unroll
                for (int j = 0; j < NK; j++) a += ET[j] * S[OFF_GR + j * W1P + tid];
                S[OFF_B1 + tid] -= lc * a;
            }
        }
        __syncthreads();

        // ---- P4 (row w): out = q + ln_fwd(Z1_bar) ----------------------------
        {
            int c0 = lane, c1 = lane + 32;
            float z0 = S[OFF_ZQ + w * W1P + c0], z1 = S[OFF_ZQ + w * W1P + c1];
            float mu = warpAllSum(z0 + z1) * (1.f / 64.f);
            float var = warpAllSum(z0 * z0 + z1 * z1) * (1.f / 64.f) - mu * mu;
            float rstd = rsqrtf(var + 1e-5f);
            int s = mb * NK + w;
            float* orow = zg + (size_t)s * NHID;
            orow[c0] = QS[c0 * DP + w] +
                       (z0 - mu) * rstd * S[OFF_GSC + c0] + S[OFF_GBI + c0];
            orow[c1] = QS[c1 * DP + w] +
                       (z1 - mu) * rstd * S[OFF_GSC + c1] + S[OFF_GBI + c1];
        }
        __syncthreads();
    }
}

// -------- post-norm + gelu(gate) product, writes split-bf16 G -----------------
__global__ __launch_bounds__(256) void postnorm_kernel(
    const float* __restrict__ pns, const float* __restrict__ pnb)
{
    int t = blockIdx.x;
    int tid = threadIdx.x;
    const float* zr = g_Z + (size_t)t * NHID;
    const float* gr = g_qvg + (size_t)t * KSP + 2 * NHID;   // gate part
    __nv_bfloat16* orow = g_asplit + (size_t)t * KSP;

    float z0 = zr[tid], z1 = zr[tid + 256], z2 = zr[tid + 512];
    float s1 = warpAllSum(z0 + z1 + z2);
    float s2 = warpAllSum(z0 * z0 + z1 * z1 + z2 * z2);
    __shared__ float sm1[8], sm2[8];
    if ((tid & 31) == 0) { sm1[tid >> 5] = s1; sm2[tid >> 5] = s2; }
    __syncthreads();
    float T1 = 0.f, T2 = 0.f;
#pragma unroll
    for (int i = 0; i < 8; i++) { T1 += sm1[i]; T2 += sm2[i]; }
    float mu = T1 * (1.f / 768.f);
    float var = T2 * (1.f / 768.f) - mu * mu;
    float rstd = rsqrtf(var + 1e-5f);
#pragma unroll
    for (int u = 0; u < 3; u++) {
        int cidx = tid + (u << 8);
        float zz = (u == 0 ? z0 : (u == 1 ? z1 : z2));
        float zn = (zz - mu) * rstd * pns[cidx] + pnb[cidx];
        float gv = gr[cidx];
        float g3 = 0.5f * gv *
                   (1.f + tanhf(0.7978845608028654f * (gv + 0.044715f * gv * gv * gv)));
        float val = zn * g3;
        __nv_bfloat16 hi = __float2bfloat16(val);
        __nv_bfloat16 lo = __float2bfloat16(val - __bfloat162float(hi));
        orow[cidx] = hi;
        orow[NHID + cidx] = lo;
        orow[2 * NHID + cidx] = hi;
    }
}

// ------------------------------- launcher ------------------------------------
#define GEMM_DSM (1024 + 6 * STAGE_BYTES)

extern "C" void kernel_launch(void* const* d_in, const int* in_sizes, int n_in,
                              void* d_out, int out_size)
{
    const float* x   = (const float*)d_in[0];
    const float* wq  = (const float*)d_in[1];
    const float* wv  = (const float*)d_in[2];
    const float* wo  = (const float*)d_in[3];
    const float* wg  = (const float*)d_in[4];
    const float* cqw = (const float*)d_in[5];
    const float* cqb = (const float*)d_in[6];
    const float* ckw = (const float*)d_in[7];
    const float* ckb = (const float*)d_in[8];
    const float* lrw = (const float*)d_in[9];
    const float* lrb = (const float*)d_in[10];
    const float* lti = (const float*)d_in[11];
    const float* tns = (const float*)d_in[12];
    const float* tnb = (const float*)d_in[13];
    const float* pns = (const float*)d_in[14];
    const float* pnb = (const float*)d_in[15];
    const float* W1  = (const float*)d_in[16];
    const float* b1  = (const float*)d_in[17];
    float* out = (float*)d_out;

    __nv_bfloat16 *p_asplit, *p_bt1, *p_bt2;
    float *p_qvg;
    cudaGetSymbolAddress((void**)&p_asplit, g_asplit);
    cudaGetSymbolAddress((void**)&p_bt1, g_bt1);
    cudaGetSymbolAddress((void**)&p_bt2, g_bt2);
    cudaGetSymbolAddress((void**)&p_qvg, g_qvg);

    cudaFuncSetAttribute(mma_gemm, cudaFuncAttributeMaxDynamicSharedMemorySize,
                         GEMM_DSM);
    cudaFuncSetAttribute(scan_kernel, cudaFuncAttributeMaxDynamicSharedMemorySize,
                         SCAN_DSM);

    split_x_kernel<<<NTOK, 256>>>(x);
    build_bt_kernel<<<KSP, 256>>>(p_bt1, wq, wv, wg);
    build_bt_kernel<<<NHID, 256>>>(p_bt2, wo, wo, wo);

    mma_gemm<<<dim3(KSP / 128, NTOK / 128), 256, GEMM_DSM>>>(p_asplit, p_bt1,
                                                             p_qvg, KSP);

    lr_kernel<<<(NTOK * 32) / 256, 256>>>(x, lrw, lrb);
    conv_rope_kernel<<<dim3(NS / 8, NB * NH), 256>>>(cqw, cqb, ckw, ckb);
    scan_kernel<<<NB * NH, 512, SCAN_DSM>>>(lti, tns, tnb, W1, b1);
    postnorm_kernel<<<NTOK, 256>>>(pns, pnb);

    mma_gemm<<<dim3(NHID / 128, NTOK / 128), 256, GEMM_DSM>>>(p_asplit, p_bt2,
                                                              out, NHID);
}

// round 7
// speedup vs baseline: 1.6894x; 1.0565x over previous
#include <cuda_runtime.h>
#include <cuda_bf16.h>
#include <math.h>
#include <stdint.h>

// Problem constants
#define NB 4
#define NS 8192
#define NHID 768
#define NH 12
#define ND 64
#define NK 16
#define NMB (NS/NK)          // 512
#define NTOK (NB*NS)         // 32768
#define KSP 2304             // split-K (3 x 768)
#define NCH 36               // K chunks of 64

// ---------------- scratch (device globals; no allocs allowed) ----------------
__device__ __nv_bfloat16 g_asplit[(size_t)NTOK*KSP]; // split A (x, later G)
__device__ float g_qvg[(size_t)NTOK*KSP];            // fused q|v|gate output f32
__device__ __nv_bfloat16 g_bt1[(size_t)KSP*KSP];     // Bt for qvg gemm
__device__ __nv_bfloat16 g_bt2[(size_t)NHID*KSP];    // Bt for wo gemm
__device__ float g_xq[(size_t)NTOK*NHID];            // [B,H, mb, r, d] row tiles
__device__ float g_xk[(size_t)NTOK*NHID];
__device__ float g_xv[(size_t)NTOK*NHID];
__device__ float g_Z[(size_t)NTOK*NHID];             // scan output [B,S,H*D]
__device__ float g_eta[NB*NH*NS];

__device__ __forceinline__ float warpAllSum(float v) {
#pragma unroll
    for (int o = 16; o; o >>= 1) v += __shfl_xor_sync(0xffffffffu, v, o);
    return v;
}

__device__ __forceinline__ uint32_t smem_u32(const void* p) {
    uint32_t a;
    asm("{ .reg .u64 t; cvta.to.shared.u64 t, %1; cvt.u32.u64 %0, t; }"
        : "=r"(a) : "l"(p));
    return a;
}

#define CPA16(sa, gp) \
    asm volatile("cp.async.cg.shared.global [%0], [%1], 16;" \
        :: "r"(sa), "l"(__cvta_generic_to_global(gp)) : "memory")
#define CPA_COMMIT() asm volatile("cp.async.commit_group;" ::: "memory")
#define CPA_WAIT2()  asm volatile("cp.async.wait_group 2;" ::: "memory")
#define CPA_WAIT1()  asm volatile("cp.async.wait_group 1;" ::: "memory")

__device__ __forceinline__ void ldsm4(uint32_t* r, uint32_t a) {
    asm volatile("ldmatrix.sync.aligned.m8n8.x4.shared.b16 {%0,%1,%2,%3}, [%4];"
        : "=r"(r[0]), "=r"(r[1]), "=r"(r[2]), "=r"(r[3]) : "r"(a));
}
__device__ __forceinline__ void mma16816(float* c, const uint32_t* a,
                                         const uint32_t* b) {
    asm volatile("mma.sync.aligned.m16n8k16.row.col.f32.bf16.bf16.f32 "
        "{%0,%1,%2,%3}, {%4,%5,%6,%7}, {%8,%9}, {%0,%1,%2,%3};"
        : "+f"(c[0]), "+f"(c[1]), "+f"(c[2]), "+f"(c[3])
        : "r"(a[0]), "r"(a[1]), "r"(a[2]), "r"(a[3]), "r"(b[0]), "r"(b[1]));
}

// ======================= mma.sync GEMM: C = A * Bt^T ==========================
#define STAGE_BYTES 16384
__global__ __launch_bounds__(256) void mma_gemm(
    const __nv_bfloat16* __restrict__ A, const __nv_bfloat16* __restrict__ Bt,
    float* __restrict__ C, int ldc)
{
    extern __shared__ char dsm[];
    uint32_t sbase = (smem_u32(dsm) + 1023u) & ~1023u;
    uint32_t aS = sbase;
    uint32_t bS = sbase + 3 * STAGE_BYTES;

    int tid = threadIdx.x, lane = tid & 31, w = tid >> 5;
    int m0 = blockIdx.y * 128, n0 = blockIdx.x * 128;
    int mw = (w & 1) * 64, nw = (w >> 1) * 32;

    int r0 = tid >> 3, cg = tid & 7;
    uint32_t st_off = (uint32_t)(r0 * 128 + ((cg * 16) ^ ((r0 & 7) << 4)));
    const __nv_bfloat16* ga = A  + (size_t)(m0 + r0) * KSP + cg * 8;
    const __nv_bfloat16* gb = Bt + (size_t)(n0 + r0) * KSP + cg * 8;

#pragma unroll
    for (int j = 0; j < 3; j++) {
#pragma unroll
        for (int t = 0; t < 4; t++) {
            CPA16(aS + j * STAGE_BYTES + st_off + t * 4096,
                  ga + (size_t)t * 32 * KSP + j * 64);
            CPA16(bS + j * STAGE_BYTES + st_off + t * 4096,
                  gb + (size_t)t * 32 * KSP + j * 64);
        }
        CPA_COMMIT();
    }

    uint32_t swz = (uint32_t)((lane & 7) << 4);
    uint32_t a_row_byte = (uint32_t)((mw + (lane & 15)) * 128);
    uint32_t a_khalf = (uint32_t)((lane >> 4) * 16);
    uint32_t b_row_byte = (uint32_t)((nw + (lane & 7) + ((lane >> 4) << 3)) * 128);
    uint32_t b_khalf = (uint32_t)(((lane >> 3) & 1) * 16);

    float cacc[4][4][4];
#pragma unroll
    for (int i = 0; i < 4; i++)
#pragma unroll
        for (int j = 0; j < 4; j++)
#pragma unroll
            for (int k = 0; k < 4; k++) cacc[i][j][k] = 0.f;

    for (int i = 0; i < NCH; i++) {
        int si = i % 3;
        CPA_WAIT2();
        __syncthreads();
        uint32_t aT = aS + si * STAGE_BYTES;
        uint32_t bT = bS + si * STAGE_BYTES;
#pragma unroll
        for (int ks = 0; ks < 4; ks++) {
            uint32_t afr[4][4], bfr[4][2];
#pragma unroll
            for (int am = 0; am < 4; am++) {
                uint32_t row_b = a_row_byte + am * (16 * 128);
                ldsm4(afr[am], aT + row_b + ((ks * 32 + a_khalf) ^ swz));
            }
#pragma unroll
            for (int bg = 0; bg < 2; bg++) {
                uint32_t t4[4];
                uint32_t row_b = b_row_byte + bg * (16 * 128);
                ldsm4(t4, bT + row_b + ((ks * 32 + b_khalf) ^ swz));
                bfr[bg * 2 + 0][0] = t4[0]; bfr[bg * 2 + 0][1] = t4[1];
                bfr[bg * 2 + 1][0] = t4[2]; bfr[bg * 2 + 1][1] = t4[3];
            }
#pragma unroll
            for (int am = 0; am < 4; am++)
#pragma unroll
                for (int bn = 0; bn < 4; bn++)
                    mma16816(cacc[am][bn], afr[am], bfr[bn]);
        }
        __syncthreads();
        int jn = i + 3;
        if (jn < NCH) {
#pragma unroll
            for (int t = 0; t < 4; t++) {
                CPA16(aS + si * STAGE_BYTES + st_off + t * 4096,
                      ga + (size_t)t * 32 * KSP + jn * 64);
                CPA16(bS + si * STAGE_BYTES + st_off + t * 4096,
                      gb + (size_t)t * 32 * KSP + jn * 64);
            }
        }
        CPA_COMMIT();
    }

    int erow = lane >> 2, ecol = (lane & 3) * 2;
#pragma unroll
    for (int am = 0; am < 4; am++) {
#pragma unroll
        for (int bn = 0; bn < 4; bn++) {
            int r = m0 + mw + am * 16 + erow;
            int c = n0 + nw + bn * 8 + ecol;
            *(float2*)&C[(size_t)r * ldc + c] =
                make_float2(cacc[am][bn][0], cacc[am][bn][1]);
            *(float2*)&C[(size_t)(r + 8) * ldc + c] =
                make_float2(cacc[am][bn][2], cacc[am][bn][3]);
        }
    }
}

// ---------------- conversion: x -> split bf16 [Ah|Al|Ah] ----------------------
__global__ __launch_bounds__(256) void split_x_kernel(const float* __restrict__ x)
{
    size_t t = blockIdx.x;
    __nv_bfloat16* dst = g_asplit + t * KSP;
    const float* src = x + t * NHID;
#pragma unroll
    for (int u = 0; u < 3; u++) {
        int cidx = threadIdx.x + (u << 8);
        float v = src[cidx];
        __nv_bfloat16 hi = __float2bfloat16(v);
        __nv_bfloat16 lo = __float2bfloat16(v - __bfloat162float(hi));
        dst[cidx] = hi;
        dst[NHID + cidx] = lo;
        dst[2 * NHID + cidx] = hi;
    }
}

// ---------------- build transposed split weights [Bh|Bh|Bl] -------------------
__global__ __launch_bounds__(256) void build_bt_kernel(
    __nv_bfloat16* __restrict__ dst, const float* __restrict__ w0,
    const float* __restrict__ w1, const float* __restrict__ w2)
{
    int np = blockIdx.x;
    int sel = np / NHID;
    const float* w = (sel == 0) ? w0 : (sel == 1) ? w1 : w2;
    int n = np % NHID;
    __nv_bfloat16* d = dst + (size_t)np * KSP;
#pragma unroll
    for (int u = 0; u < 3; u++) {
        int k = threadIdx.x + (u << 8);
        float v = w[(size_t)k * NHID + n];
        __nv_bfloat16 hi = __float2bfloat16(v);
        __nv_bfloat16 lo = __float2bfloat16(v - __bfloat162float(hi));
        d[k] = hi;
        d[NHID + k] = hi;
        d[2 * NHID + k] = lo;
    }
}

// ---------------- ttt_lr_eta = sigmoid(x . lr_w[h] + lr_b[h]) / D -------------
__global__ __launch_bounds__(256) void lr_kernel(
    const float* __restrict__ x, const float* __restrict__ lrw,
    const float* __restrict__ lrb)
{
    int gw = (blockIdx.x * blockDim.x + threadIdx.x) >> 5;
    int lane = threadIdx.x & 31;
    const float* xr = x + (size_t)gw * NHID;
    float xv[24];
#pragma unroll
    for (int u = 0; u < 24; u++) xv[u] = xr[lane + (u << 5)];
    int b = gw >> 13;
    int s = gw & (NS - 1);
    for (int h = 0; h < NH; h++) {
        const float* wr = lrw + h * NHID;
        float sum = 0.f;
#pragma unroll
        for (int u = 0; u < 24; u++) sum += xv[u] * wr[lane + (u << 5)];
        sum = warpAllSum(sum);
        if (lane == 0) {
            float zv = sum + lrb[h];
            g_eta[((size_t)b * NH + h) * NS + s] =
                (1.0f / (1.0f + expf(-zv))) * (1.0f / (float)ND);
        }
    }
}

// ------------ causal dwconv + RoPE + row-tile [bh][mb][r][d] output -----------
__global__ __launch_bounds__(256) void conv_rope_kernel(
    const float* __restrict__ cqw, const float* __restrict__ cqb,
    const float* __restrict__ ckw, const float* __restrict__ ckb)
{
    int bh = blockIdx.y;
    int b = bh / NH, h = bh % NH;
    int s = blockIdx.x * 8 + (threadIdx.x >> 5);
    int p = threadIdx.x & 31;
    int c0 = h * ND + 2 * p;

    float qe = cqb[c0], qo = cqb[c0 + 1];
    float ke = ckb[c0], ko = ckb[c0 + 1];
    const float* xb = g_qvg + ((size_t)b * NS) * KSP + c0;   // q part
#pragma unroll
    for (int kk = 0; kk < 4; kk++) {
        int ss = s + kk - 4;
        if (ss >= 0) {
            float2 xv2 = *(const float2*)(xb + (size_t)ss * KSP);
            float2 w1 = *(const float2*)(cqw + kk * NHID + c0);
            float2 w2 = *(const float2*)(ckw + kk * NHID + c0);
            qe += w1.x * xv2.x; qo += w1.y * xv2.y;
            ke += w2.x * xv2.x; ko += w2.y * xv2.y;
        }
    }
    float ex = (float)(2 * p) / (float)ND;
    float invf = (float)exp(-(double)ex * 9.210340371976184);
    float ang = (float)s * invf;
    double da = (double)ang;
    float sn = (float)sin(da), cn = (float)cos(da);

    float2 qO = make_float2(qe * cn - qo * sn, qe * sn + qo * cn);
    float2 kO = make_float2(ke * cn - ko * sn, ke * sn + ko * cn);
    float2 vv = *(const float2*)(g_qvg + ((size_t)b * NS + s) * KSP + NHID + c0);

    // row-tile layout: [(bh*NMB + mb)*1024 + r*64 + d] — fully coalesced
    size_t basep = ((size_t)bh * NMB + (size_t)(s >> 4)) * 1024 +
                   (size_t)(s & 15) * 64 + 2 * p;
    *(float2*)(g_xq + basep) = qO;
    *(float2*)(g_xk + basep) = kO;
    *(float2*)(g_xv + basep) = vv;
}

// ---------------- the sequential TTT scan: 48 blocks, 512 threads -------------
// smem float offsets
#define W1P  68
#define OFF_W1   0           // 64*68 = 4352
#define OFF_ZK   4352        // 16*68
#define OFF_ZQ   5448        // 16*68 (+8 stagger)
#define OFF_GR   6544        // 16*68
#define OFF_COEF 7632        // 16*17
#define OFF_B1   7904
#define OFF_GSC  7968
#define OFF_GBI  8032
#define OFF_TK   8096
#define OFF_ETA  8112        // 2*16
#define OFF_QKV  8144
#define ARRF 1096            // 16*68 + 8 stagger
#define BUFF (3*ARRF)        // 3288
#define SCAN_SMEM_FLOATS (OFF_QKV + 2*BUFF)    // 14720
#define SCAN_DSM (SCAN_SMEM_FLOATS * 4)

__global__ __launch_bounds__(512) void scan_kernel(
    const float* __restrict__ lti, const float* __restrict__ tns,
    const float* __restrict__ tnb, const float* __restrict__ W1g,
    const float* __restrict__ b1g)
{
    extern __shared__ float S[];
    int bh = blockIdx.x;
    int b = bh / NH, h = bh % NH;
    int tid = threadIdx.x;
    int w = tid >> 5, lane = tid & 31;

    for (int i = tid; i < ND * ND; i += 512)
        S[OFF_W1 + (i >> 6) * W1P + (i & 63)] = W1g[h * ND * ND + i];
    if (tid < ND) {
        S[OFF_B1 + tid]  = b1g[h * ND + tid];
        S[OFF_GSC + tid] = tns[h * ND + tid];
        S[OFF_GBI + tid] = tnb[h * ND + tid];
    }
    if (tid < NK)
        S[OFF_TK + tid] = fmaxf(1.0f / (float)(tid + 1) + lti[tid], 0.0f);

    const float* gq = g_xq + (size_t)bh * (NMB * 1024);
    const float* gk = g_xk + (size_t)bh * (NMB * 1024);
    const float* gv = g_xv + (size_t)bh * (NMB * 1024);
    const float* eg = g_eta + (size_t)bh * NS;
    float* zg = g_Z + (size_t)b * NS * NHID + h * ND;

    uint32_t sbase = smem_u32(S);

    // prefetch mb 0 into buffer 0: rows r of 64 floats -> [r*68 + d]
    for (int idx = tid; idx < 772; idx += 512) {
        if (idx < 768) {
            int arr = idx >> 8, rest = idx & 255, r = rest >> 4, ch = rest & 15;
            const float* src = (arr == 0 ? gq : (arr == 1 ? gk : gv)) +
                               r * 64 + ch * 4;
            CPA16(sbase + 4u * (OFF_QKV + arr * ARRF + r * W1P + ch * 4), src);
        } else {
            int ch = idx - 768;
            CPA16(sbase + 4u * (OFF_ETA + ch * 4), eg + ch * 4);
        }
    }
    CPA_COMMIT();

    for (int mb = 0; mb < NMB; mb++) {
        int buf = mb & 1;
        if (mb + 1 < NMB) {
            int nb = buf ^ 1;
            size_t goff = (size_t)(mb + 1) * 1024;
            for (int idx = tid; idx < 772; idx += 512) {
                if (idx < 768) {
                    int arr = idx >> 8, rest = idx & 255, r = rest >> 4,
                        ch = rest & 15;
                    const float* src = (arr == 0 ? gq : (arr == 1 ? gk : gv)) +
                                       goff + r * 64 + ch * 4;
                    CPA16(sbase + 4u * (OFF_QKV + nb * BUFF + arr * ARRF +
                                        r * W1P + ch * 4), src);
                } else {
                    int ch = idx - 768;
                    CPA16(sbase + 4u * (OFF_ETA + nb * 16 + ch * 4),
                          eg + (size_t)(mb + 1) * 16 + ch * 4);
                }
            }
        }
        CPA_COMMIT();
        CPA_WAIT1();
        __syncthreads();                                   // sync 1

        const float* QS = S + OFF_QKV + buf * BUFF;
        const float* KS = QS + ARRF;
        const float* VS = QS + 2 * ARRF;
        const float* ET = S + OFF_ETA + buf * 16;

        // ---- P1: merged Z1 = k@W1+b1 (hf 0) and Z1q = q@W1+b1 (hf 1) --------
        {
            int r = lane & 15, hf = lane >> 4, c4 = w << 2;
            const float* src = (hf ? QS : KS) + r * W1P;
            float a0 = S[OFF_B1 + c4],     a1 = S[OFF_B1 + c4 + 1];
            float a2 = S[OFF_B1 + c4 + 2], a3 = S[OFF_B1 + c4 + 3];
#pragma unroll
            for (int d4 = 0; d4 < ND; d4 += 4) {
                float4 sv = *(const float4*)&src[d4];
                float4 w0 = *(const float4*)&S[OFF_W1 + (d4 + 0) * W1P + c4];
                a0 += sv.x * w0.x; a1 += sv.x * w0.y;
                a2 += sv.x * w0.z; a3 += sv.x * w0.w;
                float4 w1 = *(const float4*)&S[OFF_W1 + (d4 + 1) * W1P + c4];
                a0 += sv.y * w1.x; a1 += sv.y * w1.y;
                a2 += sv.y * w1.z; a3 += sv.y * w1.w;
                float4 w2 = *(const float4*)&S[OFF_W1 + (d4 + 2) * W1P + c4];
                a0 += sv.z * w2.x; a1 += sv.z * w2.y;
                a2 += sv.z * w2.z; a3 += sv.z * w2.w;
                float4 w3 = *(const float4*)&S[OFF_W1 + (d4 + 3) * W1P + c4];
                a0 += sv.w * w3.x; a1 += sv.w * w3.y;
                a2 += sv.w * w3.z; a3 += sv.w * w3.w;
            }
            float* dst = S + (hf ? OFF_ZQ : OFF_ZK) + r * W1P + c4;
            *(float4*)dst = make_float4(a0, a1, a2, a3);
        }
        __syncthreads();                                   // sync 2

        // ---- P2 (row w): LN-L2 backward -> grad ; attn + coef ----------------
        {
            int c0 = lane, c1 = lane + 32;
            float z0 = S[OFF_ZK + w * W1P + c0], z1 = S[OFF_ZK + w * W1P + c1];
            float mu = warpAllSum(z0 + z1) * (1.f / 64.f);
            float var = warpAllSum(z0 * z0 + z1 * z1) * (1.f / 64.f) - mu * mu;
            float rstd = rsqrtf(var + 1e-5f);
            float xh0 = (z0 - mu) * rstd, xh1 = (z1 - mu) * rstd;
            float g0 = S[OFF_GSC + c0], g1 = S[OFF_GSC + c1];
            float t0 = VS[w * W1P + c0] - KS[w * W1P + c0];
            float t1 = VS[w * W1P + c1] - KS[w * W1P + c1];
            float gx0 = (xh0 * g0 + S[OFF_GBI + c0] - t0) * g0;
            float gx1 = (xh1 * g1 + S[OFF_GBI + c1] - t1) * g1;
            float m1 = warpAllSum(gx0 + gx1) * (1.f / 64.f);
            float m2 = warpAllSum(gx0 * xh0 + gx1 * xh1) * (1.f / 64.f);
            S[OFF_GR + w * W1P + c0] = (gx0 - m1 - xh0 * m2) * rstd;
            S[OFF_GR + w * W1P + c1] = (gx1 - m1 - xh1 * m2) * rstd;

            int j = lane & 15, hfa = lane >> 4;
            const float* qrow = QS + w * W1P + hfa * 32;
            const float* krow = KS + j * W1P + hfa * 32;
            float a = 0.f;
#pragma unroll 8
            for (int dd = 0; dd < 32; dd++) a += qrow[dd] * krow[dd];
            a += __shfl_xor_sync(0xffffffffu, a, 16);
            if (lane < NK)
                S[OFF_COEF + w * 17 + j] =
                    (j <= w) ? S[OFF_TK + w] * ET[j] * (a + 1.0f) : 0.0f;
        }
        __syncthreads();                                   // sync 3

        // ---- P3 (row w): z_bar = ZQ - coef@grad, LN, out ; then W1/b1 update -
        {
            int c0 = lane, c1 = lane + 32;
            float z0 = S[OFF_ZQ + w * W1P + c0], z1 = S[OFF_ZQ + w * W1P + c1];
#pragma unroll
            for (int j = 0; j < NK; j++) {
                float co = S[OFF_COEF + w * 17 + j];
                z0 -= co * S[OFF_GR + j * W1P + c0];
                z1 -= co * S[OFF_GR + j * W1P + c1];
            }
            float mu = warpAllSum(z0 + z1) * (1.f / 64.f);
            float var = warpAllSum(z0 * z0 + z1 * z1) * (1.f / 64.f) - mu * mu;
            float rstd = rsqrtf(var + 1e-5f);
            int s = mb * NK + w;
            float* orow = zg + (size_t)s * NHID;
            orow[c0] = QS[w * W1P + c0] +
                       (z0 - mu) * rstd * S[OFF_GSC + c0] + S[OFF_GBI + c0];
            orow[c1] = QS[w * W1P + c1] +
                       (z1 - mu) * rstd * S[OFF_GSC + c1] + S[OFF_GBI + c1];
        }
        {
            float lc = S[OFF_TK + NK - 1];
            int dd = tid >> 3;
            int e0 = (tid & 7) << 3;
            float4 ac0 = make_float4(0, 0, 0, 0), ac1 = make_float4(0, 0, 0, 0);
#pragma unroll
            for (int j = 0; j < NK; j++) {
                float lk = lc * ET[j] * KS[j * W1P + dd];
                float4 gj0 = *(const float4*)&S[OFF_GR + j * W1P + e0];
                float4 gj1 = *(const float4*)&S[OFF_GR + j * W1P + e0 + 4];
                ac0.x += lk * gj0.x; ac0.y += lk * gj0.y;
                ac0.z += lk * gj0.z; ac0.w += lk * gj0.w;
                ac1.x += lk * gj1.x; ac1.y += lk * gj1.y;
                ac1.z += lk * gj1.z; ac1.w += lk * gj1.w;
            }
            float4* wr0 = (float4*)&S[OFF_W1 + dd * W1P + e0];
            float4* wr1 = (float4*)&S[OFF_W1 + dd * W1P + e0 + 4];
            float4 v0 = *wr0, v1 = *wr1;
            v0.x -= ac0.x; v0.y -= ac0.y; v0.z -= ac0.z; v0.w -= ac0.w;
            v1.x -= ac1.x; v1.y -= ac1.y; v1.z -= ac1.z; v1.w -= ac1.w;
            *wr0 = v0; *wr1 = v1;
            if (tid < ND) {
                float a = 0.f;
#pragma unroll
                for (int j = 0; j < NK; j++)
                    a += ET[j] * S[OFF_GR + j * W1P + tid];
                S[OFF_B1 + tid] -= lc * a;
            }
        }
        __syncthreads();                                   // sync 4
    }
}

// -------- post-norm + gelu(gate) product, writes split-bf16 G -----------------
__global__ __launch_bounds__(256) void postnorm_kernel(
    const float* __restrict__ pns, const float* __restrict__ pnb)
{
    int t = blockIdx.x;
    int tid = threadIdx.x;
    const float* zr = g_Z + (size_t)t * NHID;
    const float* gr = g_qvg + (size_t)t * KSP + 2 * NHID;   // gate part
    __nv_bfloat16* orow = g_asplit + (size_t)t * KSP;

    float z0 = zr[tid], z1 = zr[tid + 256], z2 = zr[tid + 512];
    float s1 = warpAllSum(z0 + z1 + z2);
    float s2 = warpAllSum(z0 * z0 + z1 * z1 + z2 * z2);
    __shared__ float sm1[8], sm2[8];
    if ((tid & 31) == 0) { sm1[tid >> 5] = s1; sm2[tid >> 5] = s2; }
    __syncthreads();
    float T1 = 0.f, T2 = 0.f;
#pragma unroll
    for (int i = 0; i < 8; i++) { T1 += sm1[i]; T2 += sm2[i]; }
    float mu = T1 * (1.f / 768.f);
    float var = T2 * (1.f / 768.f) - mu * mu;
    float rstd = rsqrtf(var + 1e-5f);
#pragma unroll
    for (int u = 0; u < 3; u++) {
        int cidx = tid + (u << 8);
        float zz = (u == 0 ? z0 : (u == 1 ? z1 : z2));
        float zn = (zz - mu) * rstd * pns[cidx] + pnb[cidx];
        float gv = gr[cidx];
        float g3 = 0.5f * gv *
                   (1.f + tanhf(0.7978845608028654f * (gv + 0.044715f * gv * gv * gv)));
        float val = zn * g3;
        __nv_bfloat16 hi = __float2bfloat16(val);
        __nv_bfloat16 lo = __float2bfloat16(val - __bfloat162float(hi));
        orow[cidx] = hi;
        orow[NHID + cidx] = lo;
        orow[2 * NHID + cidx] = hi;
    }
}

// ------------------------------- launcher ------------------------------------
#define GEMM_DSM (1024 + 6 * STAGE_BYTES)

extern "C" void kernel_launch(void* const* d_in, const int* in_sizes, int n_in,
                              void* d_out, int out_size)
{
    const float* x   = (const float*)d_in[0];
    const float* wq  = (const float*)d_in[1];
    const float* wv  = (const float*)d_in[2];
    const float* wo  = (const float*)d_in[3];
    const float* wg  = (const float*)d_in[4];
    const float* cqw = (const float*)d_in[5];
    const float* cqb = (const float*)d_in[6];
    const float* ckw = (const float*)d_in[7];
    const float* ckb = (const float*)d_in[8];
    const float* lrw = (const float*)d_in[9];
    const float* lrb = (const float*)d_in[10];
    const float* lti = (const float*)d_in[11];
    const float* tns = (const float*)d_in[12];
    const float* tnb = (const float*)d_in[13];
    const float* pns = (const float*)d_in[14];
    const float* pnb = (const float*)d_in[15];
    const float* W1  = (const float*)d_in[16];
    const float* b1  = (const float*)d_in[17];
    float* out = (float*)d_out;

    __nv_bfloat16 *p_asplit, *p_bt1, *p_bt2;
    float *p_qvg;
    cudaGetSymbolAddress((void**)&p_asplit, g_asplit);
    cudaGetSymbolAddress((void**)&p_bt1, g_bt1);
    cudaGetSymbolAddress((void**)&p_bt2, g_bt2);
    cudaGetSymbolAddress((void**)&p_qvg, g_qvg);

    cudaFuncSetAttribute(mma_gemm, cudaFuncAttributeMaxDynamicSharedMemorySize,
                         GEMM_DSM);
    cudaFuncSetAttribute(scan_kernel, cudaFuncAttributeMaxDynamicSharedMemorySize,
                         SCAN_DSM);

    split_x_kernel<<<NTOK, 256>>>(x);
    build_bt_kernel<<<KSP, 256>>>(p_bt1, wq, wv, wg);
    build_bt_kernel<<<NHID, 256>>>(p_bt2, wo, wo, wo);

    mma_gemm<<<dim3(KSP / 128, NTOK / 128), 256, GEMM_DSM>>>(p_asplit, p_bt1,
                                                             p_qvg, KSP);

    lr_kernel<<<(NTOK * 32) / 256, 256>>>(x, lrw, lrb);
    conv_rope_kernel<<<dim3(NS / 8, NB * NH), 256>>>(cqw, cqb, ckw, ckb);
    scan_kernel<<<NB * NH, 512, SCAN_DSM>>>(lti, tns, tnb, W1, b1);
    postnorm_kernel<<<NTOK, 256>>>(pns, pnb);

    mma_gemm<<<dim3(NHID / 128, NTOK / 128), 256, GEMM_DSM>>>(p_asplit, p_bt2,
                                                              out, NHID);
}